// round 2
// baseline (speedup 1.0000x reference)
#include <cuda_runtime.h>
#include <math.h>

// Problem dims
#define BB 2
#define SS 1024
#define DD 768
#define HH 12
#define LL 4
#define VV 32000
#define DHH 64
#define MM (BB*SS)      // 2048 rows
#define FF (4*DD)       // 3072

// ---------------- scratch (device globals; no allocation allowed) ----------
__device__ float g_x [MM*DD];
__device__ float g_h [MM*DD];
__device__ float g_q [MM*DD];
__device__ float g_k [MM*DD];
__device__ float g_v [MM*DD];
__device__ float g_y [MM*DD];
__device__ float g_ff[MM*FF];

// ---------------- embedding + positional encoding ---------------------------
__global__ void embed_kernel(const int* __restrict__ tokens,
                             const float* __restrict__ tok_emb,
                             float* __restrict__ x)
{
    int row = blockIdx.x;           // b*S + s
    int pos = row % SS;
    int tok = tokens[row];
    const float sc = sqrtf((float)DD);
    const float negl = -logf(10000.0f) / (float)DD;
    for (int d = threadIdx.x; d < DD; d += blockDim.x) {
        int i2 = (d >> 1) << 1;                 // 2*i
        float div = __expf((float)i2 * negl);
        float ang = (float)pos * div;
        float pe = (d & 1) ? cosf(ang) : sinf(ang);
        x[(size_t)row*DD + d] = tok_emb[(size_t)tok*DD + d] * sc + pe;
    }
}

// ---------------- layernorm (row per block, 256 threads, D=768) -------------
__global__ void __launch_bounds__(256) ln_kernel(const float* __restrict__ X,
                                                 const float* __restrict__ g,
                                                 const float* __restrict__ b,
                                                 float* __restrict__ O)
{
    __shared__ float red[8];
    __shared__ float s_mean, s_rstd;
    int row = blockIdx.x, tid = threadIdx.x;
    const float* xr = X + (size_t)row*DD;
    float v0 = xr[tid], v1 = xr[tid+256], v2 = xr[tid+512];
    float s = v0 + v1 + v2;
    #pragma unroll
    for (int o = 16; o; o >>= 1) s += __shfl_xor_sync(0xffffffffu, s, o);
    if ((tid & 31) == 0) red[tid >> 5] = s;
    __syncthreads();
    if (tid == 0) {
        float t = 0.f;
        #pragma unroll
        for (int i = 0; i < 8; i++) t += red[i];
        s_mean = t / (float)DD;
    }
    __syncthreads();
    float mu = s_mean;
    float d0 = v0-mu, d1 = v1-mu, d2 = v2-mu;
    s = d0*d0 + d1*d1 + d2*d2;
    #pragma unroll
    for (int o = 16; o; o >>= 1) s += __shfl_xor_sync(0xffffffffu, s, o);
    if ((tid & 31) == 0) red[tid >> 5] = s;
    __syncthreads();
    if (tid == 0) {
        float t = 0.f;
        #pragma unroll
        for (int i = 0; i < 8; i++) t += red[i];
        s_rstd = rsqrtf(t / (float)DD + 1e-5f);
    }
    __syncthreads();
    float r = s_rstd;
    size_t base = (size_t)row*DD;
    O[base+tid    ] = d0*r*g[tid    ] + b[tid    ];
    O[base+tid+256] = d1*r*g[tid+256] + b[tid+256];
    O[base+tid+512] = d2*r*g[tid+512] + b[tid+512];
}

// ---------------- tiled SGEMM: C = act(A@W + bias [+ res]) ------------------
// A[M,K] row-major, W[K,N] row-major. 64x64 tile, BK=16, 256 threads, 4x4/thread.
// Requires M%64==0, N%64==0, K%16==0, N%4==0 (all satisfied here).
__global__ void __launch_bounds__(256) gemm_kernel(
    const float* __restrict__ A, const float* __restrict__ W,
    const float* __restrict__ bias, const float* __restrict__ res,
    float* __restrict__ C, int M, int N, int K, int gelu)
{
    __shared__ float As[16][65];
    __shared__ float Bs[16][65];
    int tid = threadIdx.x;
    int tx = tid & 15, ty = tid >> 4;
    int bm = blockIdx.y * 64, bn = blockIdx.x * 64;

    int arow  = tid >> 2;         // 0..63
    int acol4 = (tid & 3) * 4;    // 0,4,8,12
    int brow  = tid >> 4;         // 0..15
    int bcol4 = (tid & 15) * 4;   // 0..60

    const float* Aptr = A + (size_t)(bm + arow) * K + acol4;
    const float* Wptr = W + (size_t)brow * N + bn + bcol4;

    float acc[4][4] = {};
    for (int kt = 0; kt < K; kt += 16) {
        float4 av = *(const float4*)(Aptr + kt);
        As[acol4+0][arow] = av.x;
        As[acol4+1][arow] = av.y;
        As[acol4+2][arow] = av.z;
        As[acol4+3][arow] = av.w;
        float4 bv = *(const float4*)(Wptr + (size_t)kt * N);
        Bs[brow][bcol4+0] = bv.x;
        Bs[brow][bcol4+1] = bv.y;
        Bs[brow][bcol4+2] = bv.z;
        Bs[brow][bcol4+3] = bv.w;
        __syncthreads();
        #pragma unroll
        for (int k = 0; k < 16; k++) {
            float a[4], bvv[4];
            #pragma unroll
            for (int i = 0; i < 4; i++) a[i] = As[k][ty*4+i];
            #pragma unroll
            for (int j = 0; j < 4; j++) bvv[j] = Bs[k][tx*4+j];
            #pragma unroll
            for (int i = 0; i < 4; i++)
                #pragma unroll
                for (int j = 0; j < 4; j++)
                    acc[i][j] = fmaf(a[i], bvv[j], acc[i][j]);
        }
        __syncthreads();
    }
    #pragma unroll
    for (int i = 0; i < 4; i++) {
        int r = bm + ty*4 + i;
        #pragma unroll
        for (int j = 0; j < 4; j++) {
            int c = bn + tx*4 + j;
            float val = acc[i][j] + bias[c];
            if (res) val += res[(size_t)r*N + c];
            if (gelu) val = 0.5f * val * (1.0f + erff(val * 0.70710678118654752f));
            C[(size_t)r*N + c] = val;
        }
    }
}

// ---------------- causal attention: one warp per query (online softmax) -----
// Q,K,V in [B*S, D] layout with head h occupying cols [h*64, h*64+64).
__global__ void __launch_bounds__(256) attn_kernel(
    const float* __restrict__ Q, const float* __restrict__ Kt,
    const float* __restrict__ Vt, float* __restrict__ Y)
{
    int w    = (blockIdx.x << 3) + (threadIdx.x >> 5);   // global warp id
    int lane = threadIdx.x & 31;
    int qi = w % SS;
    int bh = w / SS;
    int h  = bh % HH;
    int b  = bh / HH;

    const float* qp = Q + (size_t)(b*SS + qi)*DD + h*DHH;
    float q0 = qp[lane]      * 0.125f;   // 1/sqrt(64)
    float q1 = qp[lane + 32] * 0.125f;

    const float* Kbase = Kt + (size_t)b*SS*DD + h*DHH;
    const float* Vbase = Vt + (size_t)b*SS*DD + h*DHH;

    float m = -1e30f, l = 0.f, a0 = 0.f, a1 = 0.f;
    for (int k = 0; k <= qi; k++) {
        const float* kp = Kbase + (size_t)k*DD;
        float s = q0*kp[lane] + q1*kp[lane+32];
        #pragma unroll
        for (int o = 16; o; o >>= 1) s += __shfl_xor_sync(0xffffffffu, s, o);
        float nm    = fmaxf(m, s);
        float alpha = __expf(m - nm);
        float p     = __expf(s - nm);
        l = l*alpha + p;
        const float* vp = Vbase + (size_t)k*DD;
        a0 = a0*alpha + p*vp[lane];
        a1 = a1*alpha + p*vp[lane+32];
        m = nm;
    }
    float inv = 1.f / l;
    float* yp = Y + (size_t)(b*SS + qi)*DD + h*DHH;
    yp[lane]      = a0*inv;
    yp[lane + 32] = a1*inv;
}

// ---------------- orchestration ---------------------------------------------
extern "C" void kernel_launch(void* const* d_in, const int* in_sizes, int n_in,
                              void* d_out, int out_size)
{
    const int*   tokens  = (const int*)  d_in[0];
    const float* tok_emb = (const float*)d_in[1];
    const float* Wq = (const float*)d_in[2];  const float* bq = (const float*)d_in[3];
    const float* Wk = (const float*)d_in[4];  const float* bk = (const float*)d_in[5];
    const float* Wv = (const float*)d_in[6];  const float* bv = (const float*)d_in[7];
    const float* Wo = (const float*)d_in[8];  const float* bo = (const float*)d_in[9];
    const float* ln1g = (const float*)d_in[10]; const float* ln1b = (const float*)d_in[11];
    const float* ln2g = (const float*)d_in[12]; const float* ln2b = (const float*)d_in[13];
    const float* W1 = (const float*)d_in[14]; const float* b1 = (const float*)d_in[15];
    const float* W2 = (const float*)d_in[16]; const float* b2 = (const float*)d_in[17];
    const float* lnfg = (const float*)d_in[18]; const float* lnfb = (const float*)d_in[19];
    const float* fcW = (const float*)d_in[20]; const float* fcb = (const float*)d_in[21];

    float *x, *h, *q, *k, *v, *y, *ff;
    cudaGetSymbolAddress((void**)&x,  g_x);
    cudaGetSymbolAddress((void**)&h,  g_h);
    cudaGetSymbolAddress((void**)&q,  g_q);
    cudaGetSymbolAddress((void**)&k,  g_k);
    cudaGetSymbolAddress((void**)&v,  g_v);
    cudaGetSymbolAddress((void**)&y,  g_y);
    cudaGetSymbolAddress((void**)&ff, g_ff);

    embed_kernel<<<MM, 256>>>(tokens, tok_emb, x);

    dim3 gD(DD/64, MM/64);     // N=768
    dim3 gF(FF/64, MM/64);     // N=3072
    dim3 gV(VV/64, MM/64);     // N=32000

    for (int l = 0; l < LL; l++) {
        size_t wdd = (size_t)l * DD * DD;
        ln_kernel<<<MM, 256>>>(x, ln1g + l*DD, ln1b + l*DD, h);
        gemm_kernel<<<gD, 256>>>(h, Wq + wdd, bq + l*DD, nullptr, q, MM, DD, DD, 0);
        gemm_kernel<<<gD, 256>>>(h, Wk + wdd, bk + l*DD, nullptr, k, MM, DD, DD, 0);
        gemm_kernel<<<gD, 256>>>(h, Wv + wdd, bv + l*DD, nullptr, v, MM, DD, DD, 0);
        attn_kernel<<<(BB*HH*SS)/8, 256>>>(q, k, v, y);
        gemm_kernel<<<gD, 256>>>(y, Wo + wdd, bo + l*DD, x, x, MM, DD, DD, 0);
        ln_kernel<<<MM, 256>>>(x, ln2g + l*DD, ln2b + l*DD, h);
        gemm_kernel<<<gF, 256>>>(h, W1 + (size_t)l*DD*FF, b1 + l*FF, nullptr, ff, MM, FF, DD, 1);
        gemm_kernel<<<gD, 256>>>(ff, W2 + (size_t)l*FF*DD, b2 + l*DD, x, x, MM, DD, FF, 0);
    }
    ln_kernel<<<MM, 256>>>(x, lnfg, lnfb, h);
    gemm_kernel<<<gV, 256>>>(h, fcW, fcb, nullptr, (float*)d_out, MM, VV, DD, 0);
}

// round 9
// speedup vs baseline: 2.0022x; 2.0022x over previous
#include <cuda_runtime.h>
#include <math.h>
#include <stdint.h>

#define BB 2
#define SS 1024
#define DD 768
#define HH 12
#define LL 4
#define VV 32000
#define MM (BB*SS)      // 2048
#define FF (4*DD)       // 3072
#define QKVN (3*DD)     // 2304

// ---------------- scratch (device globals) ----------------------------------
__device__ float g_x  [MM*DD];
__device__ float g_h  [MM*DD];
__device__ float g_qkv[MM*QKVN];
__device__ float g_y  [MM*DD];
__device__ float g_ff [MM*FF];
__device__ float g_bqkv[LL*QKVN];
__device__ float g_wt [52887552];   // transposed tf32-rounded weights [N][K]

#define WT_QKV   0u
#define WT_QKV_L 1769472u           // 2304*768
#define WT_O     7077888u
#define WT_O_L   589824u
#define WT_W1    9437184u
#define WT_W1_L  2359296u           // [3072][768]
#define WT_W2    18874368u
#define WT_W2_L  2359296u           // [768][3072]
#define WT_FC    28311552u          // [32000][768]

__device__ __forceinline__ uint32_t f2tf32(float f){
    uint32_t r; asm("cvt.rna.tf32.f32 %0, %1;" : "=r"(r) : "f"(f)); return r;
}
__device__ __forceinline__ float tfr(float f){ return __uint_as_float(f2tf32(f)); }

#define MMA8(d, a0,a1,a2,a3, b0,b1) \
  asm volatile("mma.sync.aligned.m16n8k8.row.col.f32.tf32.tf32.f32 " \
      "{%0,%1,%2,%3}, {%4,%5,%6,%7}, {%8,%9}, {%0,%1,%2,%3};" \
      : "+f"(d.x),"+f"(d.y),"+f"(d.z),"+f"(d.w) \
      : "r"(__float_as_uint(a0)),"r"(__float_as_uint(a1)), \
        "r"(__float_as_uint(a2)),"r"(__float_as_uint(a3)), \
        "r"(__float_as_uint(b0)),"r"(__float_as_uint(b1)))

// ---------------- embedding + positional encoding ---------------------------
__global__ void embed_kernel(const int* __restrict__ tokens,
                             const float* __restrict__ tok_emb,
                             float* __restrict__ x)
{
    int row = blockIdx.x;
    int pos = row % SS;
    int tok = tokens[row];
    const float sc = sqrtf((float)DD);
    const float negl = -logf(10000.0f) / (float)DD;
    for (int d = threadIdx.x; d < DD; d += blockDim.x) {
        int i2 = (d >> 1) << 1;
        float div = __expf((float)i2 * negl);
        float ang = (float)pos * div;
        float pe = (d & 1) ? cosf(ang) : sinf(ang);
        x[(size_t)row*DD + d] = tok_emb[(size_t)tok*DD + d] * sc + pe;
    }
}

// ---------------- layernorm --------------------------------------------------
__global__ void __launch_bounds__(256) ln_kernel(const float* __restrict__ X,
                                                 const float* __restrict__ g,
                                                 const float* __restrict__ b,
                                                 float* __restrict__ O)
{
    __shared__ float red[8];
    __shared__ float s_mean, s_rstd;
    int row = blockIdx.x, tid = threadIdx.x;
    const float* xr = X + (size_t)row*DD;
    float v0 = xr[tid], v1 = xr[tid+256], v2 = xr[tid+512];
    float s = v0 + v1 + v2;
    #pragma unroll
    for (int o = 16; o; o >>= 1) s += __shfl_xor_sync(0xffffffffu, s, o);
    if ((tid & 31) == 0) red[tid >> 5] = s;
    __syncthreads();
    if (tid == 0) {
        float t = 0.f;
        #pragma unroll
        for (int i = 0; i < 8; i++) t += red[i];
        s_mean = t / (float)DD;
    }
    __syncthreads();
    float mu = s_mean;
    float d0 = v0-mu, d1 = v1-mu, d2 = v2-mu;
    s = d0*d0 + d1*d1 + d2*d2;
    #pragma unroll
    for (int o = 16; o; o >>= 1) s += __shfl_xor_sync(0xffffffffu, s, o);
    if ((tid & 31) == 0) red[tid >> 5] = s;
    __syncthreads();
    if (tid == 0) {
        float t = 0.f;
        #pragma unroll
        for (int i = 0; i < 8; i++) t += red[i];
        s_rstd = rsqrtf(t / (float)DD + 1e-5f);
    }
    __syncthreads();
    float r = s_rstd;
    size_t base = (size_t)row*DD;
    O[base+tid    ] = d0*r*g[tid    ] + b[tid    ];
    O[base+tid+256] = d1*r*g[tid+256] + b[tid+256];
    O[base+tid+512] = d2*r*g[tid+512] + b[tid+512];
}

// ---------------- weight transpose (+tf32 round): out[N][K] = rna(in[K][N]) --
__global__ void transpose_kernel(const float* __restrict__ in, float* __restrict__ out,
                                 int K, int N)
{
    __shared__ float t[32][33];
    int nb = blockIdx.x*32, kb = blockIdx.y*32;
    int tx = threadIdx.x, ty = threadIdx.y;
    for (int i = ty; i < 32; i += 8)
        t[i][tx] = in[(size_t)(kb+i)*N + nb + tx];
    __syncthreads();
    for (int i = ty; i < 32; i += 8)
        out[(size_t)(nb+i)*K + kb + tx] = tfr(t[tx][i]);
}

// ---------------- qkv bias concat --------------------------------------------
__global__ void pack_bias(const float* __restrict__ bq, const float* __restrict__ bk,
                          const float* __restrict__ bv, float* __restrict__ out)
{
    int i = blockIdx.x*256 + threadIdx.x;
    if (i >= LL*QKVN) return;
    int l = i / QKVN, n = i % QKVN;
    float v = (n < 768) ? bq[l*768 + n]
            : (n < 1536) ? bk[l*768 + n - 768]
                         : bv[l*768 + n - 1536];
    out[i] = v;
}

// ---------------- tf32 mma.sync GEMM -----------------------------------------
// C[2048, N] = act(A[2048,K] @ Wt[N,K]^T + bias [+ res])
// CTA tile 128x64, BK=32, 8 warps (2m x 4n), warp tile 64x16 via m16n8k8.
// SMEM k-permuted: col = (k%4)*8 + k/4, row stride 36 -> LDS.128 fragments.
#define GBM 128
#define GBN 64
#define GBK 32
#define ASTR 36
#define ABUFW (GBM*ASTR)
#define BBUFW (GBN*ASTR)

__global__ void __launch_bounds__(256) mma_gemm(
    const float* __restrict__ A, const float* __restrict__ Wt,
    const float* __restrict__ bias, const float* __restrict__ res,
    float* __restrict__ C, int N, int K, int act)
{
    extern __shared__ float sm[];
    float* As = sm;                  // 2 * ABUFW
    float* Bs = sm + 2*ABUFW;        // 2 * BBUFW

    int tid = threadIdx.x;
    int wid = tid >> 5, lane = tid & 31;
    int g = lane >> 2, t = lane & 3;
    int wm = wid & 1, wn = wid >> 1;
    int bm = blockIdx.x * GBM, bn = blockIdx.y * GBN;

    int srow = tid >> 3, scol = tid & 7;
    const float* Abase = A  + (size_t)(bm + srow)*K + scol*4;
    const float* Bbase = Wt + (size_t)(bn + srow)*K + scol*4;

    float4 ra[4], rb[2];
    float4 acc[4][2];
    #pragma unroll
    for (int i = 0; i < 4; i++)
        #pragma unroll
        for (int j = 0; j < 2; j++)
            acc[i][j] = make_float4(0.f,0.f,0.f,0.f);

    // prologue load k-tile 0
    #pragma unroll
    for (int i = 0; i < 4; i++) ra[i] = *(const float4*)(Abase + (size_t)(32*i)*K);
    #pragma unroll
    for (int i = 0; i < 2; i++) rb[i] = *(const float4*)(Bbase + (size_t)(32*i)*K);
    {
        #pragma unroll
        for (int i = 0; i < 4; i++){
            float* p = As + (srow + 32*i)*ASTR + scol;
            p[0] = tfr(ra[i].x); p[8] = tfr(ra[i].y); p[16] = tfr(ra[i].z); p[24] = tfr(ra[i].w);
        }
        #pragma unroll
        for (int i = 0; i < 2; i++){
            float* p = Bs + (srow + 32*i)*ASTR + scol;
            p[0] = tfr(rb[i].x); p[8] = tfr(rb[i].y); p[16] = tfr(rb[i].z); p[24] = tfr(rb[i].w);
        }
    }
    __syncthreads();

    const int NK = K / GBK;
    for (int kt = 0; kt < NK; kt++){
        int cur = kt & 1;
        if (kt + 1 < NK){
            const float* Ak = Abase + (size_t)(kt+1)*GBK;
            const float* Bk = Bbase + (size_t)(kt+1)*GBK;
            #pragma unroll
            for (int i = 0; i < 4; i++) ra[i] = *(const float4*)(Ak + (size_t)(32*i)*K);
            #pragma unroll
            for (int i = 0; i < 2; i++) rb[i] = *(const float4*)(Bk + (size_t)(32*i)*K);
        }
        // compute on buffer cur
        const float* Ac = As + cur*ABUFW;
        const float* Bc = Bs + cur*BBUFW;
        #pragma unroll
        for (int j = 0; j < 2; j++){
            float4 alo[4], ahi[4], bf[2];
            #pragma unroll
            for (int mt = 0; mt < 4; mt++){
                int r = wm*64 + mt*16 + g;
                alo[mt] = *(const float4*)(Ac + r*ASTR + t*8 + 4*j);
                ahi[mt] = *(const float4*)(Ac + (r+8)*ASTR + t*8 + 4*j);
            }
            #pragma unroll
            for (int nt = 0; nt < 2; nt++){
                int r = wn*16 + nt*8 + g;
                bf[nt] = *(const float4*)(Bc + r*ASTR + t*8 + 4*j);
            }
            #pragma unroll
            for (int mt = 0; mt < 4; mt++)
                #pragma unroll
                for (int nt = 0; nt < 2; nt++){
                    MMA8(acc[mt][nt], alo[mt].x, ahi[mt].x, alo[mt].y, ahi[mt].y,
                         bf[nt].x, bf[nt].y);
                    MMA8(acc[mt][nt], alo[mt].z, ahi[mt].z, alo[mt].w, ahi[mt].w,
                         bf[nt].z, bf[nt].w);
                }
        }
        if (kt + 1 < NK){
            int nxt = cur ^ 1;
            float* dA = As + nxt*ABUFW;
            float* dB = Bs + nxt*BBUFW;
            #pragma unroll
            for (int i = 0; i < 4; i++){
                float* p = dA + (srow + 32*i)*ASTR + scol;
                p[0] = tfr(ra[i].x); p[8] = tfr(ra[i].y); p[16] = tfr(ra[i].z); p[24] = tfr(ra[i].w);
            }
            #pragma unroll
            for (int i = 0; i < 2; i++){
                float* p = dB + (srow + 32*i)*ASTR + scol;
                p[0] = tfr(rb[i].x); p[8] = tfr(rb[i].y); p[16] = tfr(rb[i].z); p[24] = tfr(rb[i].w);
            }
            __syncthreads();
        }
    }

    // epilogue: direct STG with bias/res/act
    #pragma unroll
    for (int mt = 0; mt < 4; mt++){
        int r0 = bm + wm*64 + mt*16 + g;
        #pragma unroll
        for (int nt = 0; nt < 2; nt++){
            int col = bn + wn*16 + nt*8 + 2*t;
            float b0 = bias[col], b1 = bias[col+1];
            float4 c = acc[mt][nt];
            float v0 = c.x + b0, v1 = c.y + b1;
            float w0 = c.z + b0, w1 = c.w + b1;
            if (res){
                v0 += res[(size_t)r0*N + col];     v1 += res[(size_t)r0*N + col + 1];
                w0 += res[(size_t)(r0+8)*N + col]; w1 += res[(size_t)(r0+8)*N + col + 1];
            }
            if (act){
                v0 = 0.5f*v0*(1.0f + erff(v0*0.70710678118654752f));
                v1 = 0.5f*v1*(1.0f + erff(v1*0.70710678118654752f));
                w0 = 0.5f*w0*(1.0f + erff(w0*0.70710678118654752f));
                w1 = 0.5f*w1*(1.0f + erff(w1*0.70710678118654752f));
            }
            *(float2*)(C + (size_t)r0*N + col)     = make_float2(v0, v1);
            *(float2*)(C + (size_t)(r0+8)*N + col) = make_float2(w0, w1);
        }
    }
}

// ---------------- attention: warp/query, 8 keys/iter, group-local softmax ----
// QKV layout [B*S, 2304]: q at +0, k at +768, v at +1536 (head h at +h*64)
// NOTE: dot-product + shuffles executed by ALL lanes every iteration (reads are
// provably in-bounds: s <= (qi>>3)*8+7 <= 1023); the causal predicate gates
// only the lane-local softmax-state update. No divergent __shfl_sync.
__global__ void __launch_bounds__(256) attn_kernel(const float* __restrict__ QKV,
                                                   float* __restrict__ Y)
{
    int wid = threadIdx.x >> 5, lane = threadIdx.x & 31;
    int g  = lane >> 2;     // key slot 0..7
    int qd = lane & 3;      // dim quarter (16 dims)
    int blk  = blockIdx.x;
    int qblk = blk & 127;       // SS/8
    int bh   = blk >> 7;
    int h = bh % HH, b = bh / HH;
    int qi = qblk*8 + wid;

    const float* qr = QKV + (size_t)(b*SS + qi)*QKVN + h*64 + qd*16;
    float4 q0 = *(const float4*)(qr+0),  q1 = *(const float4*)(qr+4);
    float4 q2 = *(const float4*)(qr+8),  q3 = *(const float4*)(qr+12);
    const float s8 = 0.125f;
    q0.x*=s8;q0.y*=s8;q0.z*=s8;q0.w*=s8; q1.x*=s8;q1.y*=s8;q1.z*=s8;q1.w*=s8;
    q2.x*=s8;q2.y*=s8;q2.z*=s8;q2.w*=s8; q3.x*=s8;q3.y*=s8;q3.z*=s8;q3.w*=s8;

    const float* Kb = QKV + (size_t)b*SS*QKVN + 768  + h*64 + qd*16;
    const float* Vb = QKV + (size_t)b*SS*QKVN + 1536 + h*64 + qd*16;

    float m = -1e30f, l = 0.f;
    float acc[16];
    #pragma unroll
    for (int j = 0; j < 16; j++) acc[j] = 0.f;

    int nit = (qi >> 3) + 1;
    for (int it = 0; it < nit; it++){
        int s = it*8 + g;                    // always <= 1023 (in-bounds)
        const float* kr = Kb + (size_t)s*QKVN;
        float4 k0 = *(const float4*)(kr+0),  k1 = *(const float4*)(kr+4);
        float4 k2 = *(const float4*)(kr+8),  k3 = *(const float4*)(kr+12);
        float ss = q0.x*k0.x + q0.y*k0.y + q0.z*k0.z + q0.w*k0.w
                 + q1.x*k1.x + q1.y*k1.y + q1.z*k1.z + q1.w*k1.w
                 + q2.x*k2.x + q2.y*k2.y + q2.z*k2.z + q2.w*k2.w
                 + q3.x*k3.x + q3.y*k3.y + q3.z*k3.z + q3.w*k3.w;
        // uniform reduction over the 4 qd lanes of this key slot
        ss += __shfl_xor_sync(0xffffffffu, ss, 1);
        ss += __shfl_xor_sync(0xffffffffu, ss, 2);
        if (s <= qi){                        // lane-local update only
            float nm = fmaxf(m, ss);
            float alpha = __expf(m - nm);
            float p = __expf(ss - nm);
            l = l*alpha + p;
            const float* vr = Vb + (size_t)s*QKVN;
            float4 v0 = *(const float4*)(vr+0),  v1 = *(const float4*)(vr+4);
            float4 v2 = *(const float4*)(vr+8),  v3 = *(const float4*)(vr+12);
            acc[0]=acc[0]*alpha+p*v0.x; acc[1]=acc[1]*alpha+p*v0.y;
            acc[2]=acc[2]*alpha+p*v0.z; acc[3]=acc[3]*alpha+p*v0.w;
            acc[4]=acc[4]*alpha+p*v1.x; acc[5]=acc[5]*alpha+p*v1.y;
            acc[6]=acc[6]*alpha+p*v1.z; acc[7]=acc[7]*alpha+p*v1.w;
            acc[8]=acc[8]*alpha+p*v2.x; acc[9]=acc[9]*alpha+p*v2.y;
            acc[10]=acc[10]*alpha+p*v2.z; acc[11]=acc[11]*alpha+p*v2.w;
            acc[12]=acc[12]*alpha+p*v3.x; acc[13]=acc[13]*alpha+p*v3.y;
            acc[14]=acc[14]*alpha+p*v3.z; acc[15]=acc[15]*alpha+p*v3.w;
            m = nm;
        }
    }

    // merge 8 group-local softmaxes (across g, same qd) — uniform shfls
    #pragma unroll
    for (int mask = 4; mask < 32; mask <<= 1){
        float m2 = __shfl_xor_sync(0xffffffffu, m, mask);
        float l2 = __shfl_xor_sync(0xffffffffu, l, mask);
        float nm = fmaxf(m, m2);
        float a1 = __expf(m - nm), a2 = __expf(m2 - nm);
        l = l*a1 + l2*a2;
        #pragma unroll
        for (int j = 0; j < 16; j++){
            float o = __shfl_xor_sync(0xffffffffu, acc[j], mask);
            acc[j] = acc[j]*a1 + o*a2;
        }
        m = nm;
    }
    if (g == 0){
        float inv = 1.f / l;
        float* yr = Y + (size_t)(b*SS + qi)*DD + h*64 + qd*16;
        #pragma unroll
        for (int j = 0; j < 4; j++){
            float4 o = { acc[j*4]*inv, acc[j*4+1]*inv, acc[j*4+2]*inv, acc[j*4+3]*inv };
            *(float4*)(yr + j*4) = o;
        }
    }
}

// ---------------- orchestration ---------------------------------------------
extern "C" void kernel_launch(void* const* d_in, const int* in_sizes, int n_in,
                              void* d_out, int out_size)
{
    const int*   tokens  = (const int*)  d_in[0];
    const float* tok_emb = (const float*)d_in[1];
    const float* Wq = (const float*)d_in[2];  const float* bq = (const float*)d_in[3];
    const float* Wk = (const float*)d_in[4];  const float* bk = (const float*)d_in[5];
    const float* Wv = (const float*)d_in[6];  const float* bv = (const float*)d_in[7];
    const float* Wo = (const float*)d_in[8];  const float* bo = (const float*)d_in[9];
    const float* ln1g = (const float*)d_in[10]; const float* ln1b = (const float*)d_in[11];
    const float* ln2g = (const float*)d_in[12]; const float* ln2b = (const float*)d_in[13];
    const float* W1 = (const float*)d_in[14]; const float* b1 = (const float*)d_in[15];
    const float* W2 = (const float*)d_in[16]; const float* b2 = (const float*)d_in[17];
    const float* lnfg = (const float*)d_in[18]; const float* lnfb = (const float*)d_in[19];
    const float* fcW = (const float*)d_in[20]; const float* fcb = (const float*)d_in[21];

    float *x, *h, *qkv, *y, *ff, *bqkv, *wt;
    cudaGetSymbolAddress((void**)&x,    g_x);
    cudaGetSymbolAddress((void**)&h,    g_h);
    cudaGetSymbolAddress((void**)&qkv,  g_qkv);
    cudaGetSymbolAddress((void**)&y,    g_y);
    cudaGetSymbolAddress((void**)&ff,   g_ff);
    cudaGetSymbolAddress((void**)&bqkv, g_bqkv);
    cudaGetSymbolAddress((void**)&wt,   g_wt);

    const int SMEMB = (2*ABUFW + 2*BBUFW) * 4;   // 55296 bytes
    cudaFuncSetAttribute(mma_gemm, cudaFuncAttributeMaxDynamicSharedMemorySize, SMEMB);

    dim3 tb(32, 8);
    for (int l = 0; l < LL; l++){
        size_t wdd = (size_t)l * DD * DD;
        transpose_kernel<<<dim3(DD/32, DD/32), tb>>>(Wq + wdd, wt + WT_QKV + l*WT_QKV_L,            DD, DD);
        transpose_kernel<<<dim3(DD/32, DD/32), tb>>>(Wk + wdd, wt + WT_QKV + l*WT_QKV_L + 768*768,  DD, DD);
        transpose_kernel<<<dim3(DD/32, DD/32), tb>>>(Wv + wdd, wt + WT_QKV + l*WT_QKV_L + 1536*768, DD, DD);
        transpose_kernel<<<dim3(DD/32, DD/32), tb>>>(Wo + wdd, wt + WT_O + l*WT_O_L, DD, DD);
        transpose_kernel<<<dim3(FF/32, DD/32), tb>>>(W1 + (size_t)l*DD*FF, wt + WT_W1 + l*WT_W1_L, DD, FF);
        transpose_kernel<<<dim3(DD/32, FF/32), tb>>>(W2 + (size_t)l*FF*DD, wt + WT_W2 + l*WT_W2_L, FF, DD);
    }
    transpose_kernel<<<dim3(VV/32, DD/32), tb>>>(fcW, wt + WT_FC, DD, VV);
    pack_bias<<<(LL*QKVN + 255)/256, 256>>>(bq, bk, bv, bqkv);

    embed_kernel<<<MM, 256>>>(tokens, tok_emb, x);

    for (int l = 0; l < LL; l++){
        ln_kernel<<<MM, 256>>>(x, ln1g + l*DD, ln1b + l*DD, h);
        mma_gemm<<<dim3(MM/GBM, QKVN/GBN), 256, SMEMB>>>(h, wt + WT_QKV + l*WT_QKV_L,
                                                         bqkv + l*QKVN, nullptr, qkv, QKVN, DD, 0);
        attn_kernel<<<BB*HH*(SS/8), 256>>>(qkv, y);
        mma_gemm<<<dim3(MM/GBM, DD/GBN), 256, SMEMB>>>(y, wt + WT_O + l*WT_O_L,
                                                       bo + l*DD, x, x, DD, DD, 0);
        ln_kernel<<<MM, 256>>>(x, ln2g + l*DD, ln2b + l*DD, h);
        mma_gemm<<<dim3(MM/GBM, FF/GBN), 256, SMEMB>>>(h, wt + WT_W1 + l*WT_W1_L,
                                                       b1 + l*FF, nullptr, ff, FF, DD, 1);
        mma_gemm<<<dim3(MM/GBM, DD/GBN), 256, SMEMB>>>(ff, wt + WT_W2 + l*WT_W2_L,
                                                       b2 + l*DD, x, x, DD, FF, 0);
    }
    ln_kernel<<<MM, 256>>>(x, lnfg, lnfb, h);
    mma_gemm<<<dim3(MM/GBM, VV/GBN), 256, SMEMB>>>(h, wt + WT_FC, fcb, nullptr,
                                                   (float*)d_out, VV, DD, 0);
}

// round 10
// speedup vs baseline: 2.0557x; 1.0267x over previous
#include <cuda_runtime.h>
#include <math.h>
#include <stdint.h>

#define BB 2
#define SS 1024
#define DD 768
#define HH 12
#define LL 4
#define VV 32000
#define MM (BB*SS)      // 2048
#define FF (4*DD)       // 3072
#define QKVN (3*DD)     // 2304

// ---------------- scratch (device globals) ----------------------------------
__device__ float g_x  [MM*DD];
__device__ float g_h  [MM*DD];
__device__ float g_qkv[MM*QKVN];
__device__ float g_y  [MM*DD];
__device__ float g_ff [MM*FF];
__device__ float g_bqkv[LL*QKVN];
__device__ float g_wt [52887552];   // tf32-rounded weights, [K][N] layout

#define WT_QKV   0u
#define WT_QKV_L 1769472u           // [768][2304] per layer
#define WT_O     7077888u
#define WT_O_L   589824u            // [768][768]
#define WT_W1    9437184u
#define WT_W1_L  2359296u           // [768][3072]
#define WT_W2    18874368u
#define WT_W2_L  2359296u           // [3072][768]
#define WT_FC    28311552u          // [768][32000]

__device__ __forceinline__ uint32_t f2tf32(float f){
    uint32_t r; asm("cvt.rna.tf32.f32 %0, %1;" : "=r"(r) : "f"(f)); return r;
}
__device__ __forceinline__ float tfr(float f){ return __uint_as_float(f2tf32(f)); }
__device__ __forceinline__ uint32_t smem_u32(const void* p){
    uint32_t r;
    asm("{ .reg .u64 t; cvta.to.shared.u64 t, %1; cvt.u32.u64 %0, t; }" : "=r"(r) : "l"(p));
    return r;
}

#define MMA8(d, a0,a1,a2,a3, b0,b1) \
  asm volatile("mma.sync.aligned.m16n8k8.row.col.f32.tf32.tf32.f32 " \
      "{%0,%1,%2,%3}, {%4,%5,%6,%7}, {%8,%9}, {%0,%1,%2,%3};" \
      : "+f"(d.x),"+f"(d.y),"+f"(d.z),"+f"(d.w) \
      : "r"(__float_as_uint(a0)),"r"(__float_as_uint(a1)), \
        "r"(__float_as_uint(a2)),"r"(__float_as_uint(a3)), \
        "r"(__float_as_uint(b0)),"r"(__float_as_uint(b1)))

#define CP_ASYNC16(dst, src) \
  asm volatile("cp.async.cg.shared.global [%0], [%1], 16;" :: "r"(dst), "l"(src))
#define CP_COMMIT()  asm volatile("cp.async.commit_group;" ::: "memory")
#define CP_WAIT0()   asm volatile("cp.async.wait_group 0;" ::: "memory")

// ---------------- embedding + positional encoding ---------------------------
__global__ void embed_kernel(const int* __restrict__ tokens,
                             const float* __restrict__ tok_emb,
                             float* __restrict__ x)
{
    int row = blockIdx.x;
    int pos = row % SS;
    int tok = tokens[row];
    const float sc = sqrtf((float)DD);
    const float negl = -logf(10000.0f) / (float)DD;
    for (int d = threadIdx.x; d < DD; d += blockDim.x) {
        int i2 = (d >> 1) << 1;
        float div = __expf((float)i2 * negl);
        float ang = (float)pos * div;
        float pe = (d & 1) ? cosf(ang) : sinf(ang);
        x[(size_t)row*DD + d] = tok_emb[(size_t)tok*DD + d] * sc + pe;
    }
}

// ---------------- layernorm --------------------------------------------------
__global__ void __launch_bounds__(256) ln_kernel(const float* __restrict__ X,
                                                 const float* __restrict__ g,
                                                 const float* __restrict__ b,
                                                 float* __restrict__ O)
{
    __shared__ float red[8];
    __shared__ float s_mean, s_rstd;
    int row = blockIdx.x, tid = threadIdx.x;
    const float* xr = X + (size_t)row*DD;
    float v0 = xr[tid], v1 = xr[tid+256], v2 = xr[tid+512];
    float s = v0 + v1 + v2;
    #pragma unroll
    for (int o = 16; o; o >>= 1) s += __shfl_xor_sync(0xffffffffu, s, o);
    if ((tid & 31) == 0) red[tid >> 5] = s;
    __syncthreads();
    if (tid == 0) {
        float t = 0.f;
        #pragma unroll
        for (int i = 0; i < 8; i++) t += red[i];
        s_mean = t / (float)DD;
    }
    __syncthreads();
    float mu = s_mean;
    float d0 = v0-mu, d1 = v1-mu, d2 = v2-mu;
    s = d0*d0 + d1*d1 + d2*d2;
    #pragma unroll
    for (int o = 16; o; o >>= 1) s += __shfl_xor_sync(0xffffffffu, s, o);
    if ((tid & 31) == 0) red[tid >> 5] = s;
    __syncthreads();
    if (tid == 0) {
        float t = 0.f;
        #pragma unroll
        for (int i = 0; i < 8; i++) t += red[i];
        s_rstd = rsqrtf(t / (float)DD + 1e-5f);
    }
    __syncthreads();
    float r = s_rstd;
    size_t base = (size_t)row*DD;
    O[base+tid    ] = d0*r*g[tid    ] + b[tid    ];
    O[base+tid+256] = d1*r*g[tid+256] + b[tid+256];
    O[base+tid+512] = d2*r*g[tid+512] + b[tid+512];
}

// ---------------- pre-pass: coalesced tf32 round copies ----------------------
__global__ void round_copy(const float* __restrict__ in, float* __restrict__ out, int n4)
{
    int i = blockIdx.x*256 + threadIdx.x;
    if (i < n4){
        float4 v = ((const float4*)in)[i];
        ((float4*)out)[i] = make_float4(tfr(v.x), tfr(v.y), tfr(v.z), tfr(v.w));
    }
}

// build fused [768][2304] = [Wq | Wk | Wv] per layer (tf32-rounded), [K][N]
__global__ void pack_qkvw(const float* __restrict__ Wq, const float* __restrict__ Wk,
                          const float* __restrict__ Wv, float* __restrict__ out)
{
    int i = blockIdx.x*256 + threadIdx.x;           // float4 index
    const int total4 = LL*768*2304/4;
    if (i >= total4) return;
    int n4 = i % 576;                               // 2304/4
    int lk = i / 576;                               // l*768 + k
    int sel = n4 / 192;                             // which of q/k/v
    int n4s = n4 - sel*192;
    const float* src = (sel == 0) ? Wq : (sel == 1) ? Wk : Wv;
    float4 v = ((const float4*)src)[(size_t)lk*192 + n4s];
    ((float4*)out)[i] = make_float4(tfr(v.x), tfr(v.y), tfr(v.z), tfr(v.w));
}

// ---------------- qkv bias concat --------------------------------------------
__global__ void pack_bias(const float* __restrict__ bq, const float* __restrict__ bk,
                          const float* __restrict__ bv, float* __restrict__ out)
{
    int i = blockIdx.x*256 + threadIdx.x;
    if (i >= LL*QKVN) return;
    int l = i / QKVN, n = i % QKVN;
    float v = (n < 768) ? bq[l*768 + n]
            : (n < 1536) ? bk[l*768 + n - 768]
                         : bv[l*768 + n - 1536];
    out[i] = v;
}

// ---------------- tf32 mma.sync GEMM, B native [K][N] via cp.async -----------
// C[2048, N] = act(A[2048,K] @ B[K,N] + bias [+ res])
// CTA tile 128 x (32*WNT), BK=32, 8 warps (2m x 4n), warp tile 64 x (8*WNT).
// A: register-staged +tf32 round, k-permuted SMEM (c = 8*(k%4)+k/4, pitch 36).
// B: cp.async 16B chunks into [k][n] SMEM (pitch BN+4), fragments via LDS.32.
template<int WNT, int MINB>
__global__ void __launch_bounds__(256, MINB) mma_gemm(
    const float* __restrict__ A, const float* __restrict__ B,
    const float* __restrict__ bias, const float* __restrict__ res,
    float* __restrict__ C, int N, int K, int act)
{
    const int BN  = 32*WNT;
    const int BNP = BN + 4;
    extern __shared__ float sm[];
    float* As = sm;                        // 2 * 128*36
    float* Bs = sm + 2*128*36;             // 2 * 32*BNP
    uint32_t uBs = smem_u32(Bs);

    int tid = threadIdx.x;
    int wid = tid >> 5, lane = tid & 31;
    int g = lane >> 2, t = lane & 3;
    int wm = wid & 1, wn = wid >> 1;
    int bm = blockIdx.x * 128, bn = blockIdx.y * BN;

    int srow = tid >> 3, scol = tid & 7;
    const float* Abase = A + (size_t)(bm + srow)*K + scol*4;

    float4 ra[4];
    float4 acc[4][WNT];
    #pragma unroll
    for (int i = 0; i < 4; i++)
        #pragma unroll
        for (int j = 0; j < WNT; j++)
            acc[i][j] = make_float4(0.f,0.f,0.f,0.f);

    auto ldA = [&](int kt){
        const float* Ak = Abase + (size_t)kt*32;
        #pragma unroll
        for (int i = 0; i < 4; i++) ra[i] = *(const float4*)(Ak + (size_t)(32*i)*K);
    };
    auto stA = [&](int buf){
        float* dA = As + buf*(128*36);
        #pragma unroll
        for (int i = 0; i < 4; i++){
            float* p = dA + (srow + 32*i)*36 + scol;
            p[0]=tfr(ra[i].x); p[8]=tfr(ra[i].y); p[16]=tfr(ra[i].z); p[24]=tfr(ra[i].w);
        }
    };
    auto cpB = [&](int kt, int buf){
        const float* Bg = B + (size_t)kt*32*N + bn;
        uint32_t dst = uBs + buf*(32*BNP*4);
        if (WNT == 4){
            int row = tid >> 5, ch = tid & 31;
            #pragma unroll
            for (int i = 0; i < 4; i++){
                uint32_t d = dst + (uint32_t)(((row + 8*i)*BNP + ch*4)*4);
                const float* s = Bg + (size_t)(row + 8*i)*N + ch*4;
                CP_ASYNC16(d, s);
            }
        } else {
            int row = tid >> 4, ch = tid & 15;
            #pragma unroll
            for (int i = 0; i < 2; i++){
                uint32_t d = dst + (uint32_t)(((row + 16*i)*BNP + ch*4)*4);
                const float* s = Bg + (size_t)(row + 16*i)*N + ch*4;
                CP_ASYNC16(d, s);
            }
        }
        CP_COMMIT();
    };

    ldA(0); stA(0); cpB(0, 0);
    CP_WAIT0();
    __syncthreads();

    const int NK = K / 32;
    for (int kt = 0; kt < NK; kt++){
        int cur = kt & 1;
        if (kt + 1 < NK){ ldA(kt+1); cpB(kt+1, cur^1); }
        const float* Ac = As + cur*(128*36);
        const float* Bc = Bs + cur*(32*BNP);
        #pragma unroll
        for (int j = 0; j < 2; j++){
            float4 alo[4], ahi[4];
            #pragma unroll
            for (int mt = 0; mt < 4; mt++){
                int r = wm*64 + mt*16 + g;
                alo[mt] = *(const float4*)(Ac + r*36 + t*8 + 4*j);
                ahi[mt] = *(const float4*)(Ac + (r+8)*36 + t*8 + 4*j);
            }
            #pragma unroll
            for (int nt = 0; nt < WNT; nt++){
                int n = wn*(8*WNT) + nt*8 + g;
                float b0 = Bc[(16*j + t     )*BNP + n];
                float b1 = Bc[(16*j + t + 4 )*BNP + n];
                float b2 = Bc[(16*j + t + 8 )*BNP + n];
                float b3 = Bc[(16*j + t + 12)*BNP + n];
                #pragma unroll
                for (int mt = 0; mt < 4; mt++){
                    MMA8(acc[mt][nt], alo[mt].x, ahi[mt].x, alo[mt].y, ahi[mt].y, b0, b1);
                    MMA8(acc[mt][nt], alo[mt].z, ahi[mt].z, alo[mt].w, ahi[mt].w, b2, b3);
                }
            }
        }
        if (kt + 1 < NK){
            stA(cur^1);
            CP_WAIT0();
            __syncthreads();
        }
    }

    // epilogue: direct STG with bias/res/act
    #pragma unroll
    for (int mt = 0; mt < 4; mt++){
        int r0 = bm + wm*64 + mt*16 + g;
        #pragma unroll
        for (int nt = 0; nt < WNT; nt++){
            int col = bn + wn*(8*WNT) + nt*8 + 2*t;
            float b0 = bias[col], b1 = bias[col+1];
            float4 c = acc[mt][nt];
            float v0 = c.x + b0, v1 = c.y + b1;
            float w0 = c.z + b0, w1 = c.w + b1;
            if (res){
                v0 += res[(size_t)r0*N + col];     v1 += res[(size_t)r0*N + col + 1];
                w0 += res[(size_t)(r0+8)*N + col]; w1 += res[(size_t)(r0+8)*N + col + 1];
            }
            if (act){
                v0 = 0.5f*v0*(1.0f + erff(v0*0.70710678118654752f));
                v1 = 0.5f*v1*(1.0f + erff(v1*0.70710678118654752f));
                w0 = 0.5f*w0*(1.0f + erff(w0*0.70710678118654752f));
                w1 = 0.5f*w1*(1.0f + erff(w1*0.70710678118654752f));
            }
            *(float2*)(C + (size_t)r0*N + col)     = make_float2(v0, v1);
            *(float2*)(C + (size_t)(r0+8)*N + col) = make_float2(w0, w1);
        }
    }
}

// ---------------- attention: warp/query, 8 keys/iter, group-local softmax ----
// QKV layout [B*S, 2304]: q at +0, k at +768, v at +1536 (head h at +h*64)
__global__ void __launch_bounds__(256) attn_kernel(const float* __restrict__ QKV,
                                                   float* __restrict__ Y)
{
    int wid = threadIdx.x >> 5, lane = threadIdx.x & 31;
    int g  = lane >> 2;
    int qd = lane & 3;
    int blk  = blockIdx.x;
    int qblk = blk & 127;
    int bh   = blk >> 7;
    int h = bh % HH, b = bh / HH;
    int qi = qblk*8 + wid;

    const float* qr = QKV + (size_t)(b*SS + qi)*QKVN + h*64 + qd*16;
    float4 q0 = *(const float4*)(qr+0),  q1 = *(const float4*)(qr+4);
    float4 q2 = *(const float4*)(qr+8),  q3 = *(const float4*)(qr+12);
    const float s8 = 0.125f;
    q0.x*=s8;q0.y*=s8;q0.z*=s8;q0.w*=s8; q1.x*=s8;q1.y*=s8;q1.z*=s8;q1.w*=s8;
    q2.x*=s8;q2.y*=s8;q2.z*=s8;q2.w*=s8; q3.x*=s8;q3.y*=s8;q3.z*=s8;q3.w*=s8;

    const float* Kb = QKV + (size_t)b*SS*QKVN + 768  + h*64 + qd*16;
    const float* Vb = QKV + (size_t)b*SS*QKVN + 1536 + h*64 + qd*16;

    float m = -1e30f, l = 0.f;
    float acc[16];
    #pragma unroll
    for (int j = 0; j < 16; j++) acc[j] = 0.f;

    int nit = (qi >> 3) + 1;
    for (int it = 0; it < nit; it++){
        int s = it*8 + g;
        const float* kr = Kb + (size_t)s*QKVN;
        float4 k0 = *(const float4*)(kr+0),  k1 = *(const float4*)(kr+4);
        float4 k2 = *(const float4*)(kr+8),  k3 = *(const float4*)(kr+12);
        float ss = q0.x*k0.x + q0.y*k0.y + q0.z*k0.z + q0.w*k0.w
                 + q1.x*k1.x + q1.y*k1.y + q1.z*k1.z + q1.w*k1.w
                 + q2.x*k2.x + q2.y*k2.y + q2.z*k2.z + q2.w*k2.w
                 + q3.x*k3.x + q3.y*k3.y + q3.z*k3.z + q3.w*k3.w;
        ss += __shfl_xor_sync(0xffffffffu, ss, 1);
        ss += __shfl_xor_sync(0xffffffffu, ss, 2);
        if (s <= qi){
            float nm = fmaxf(m, ss);
            float alpha = __expf(m - nm);
            float p = __expf(ss - nm);
            l = l*alpha + p;
            const float* vr = Vb + (size_t)s*QKVN;
            float4 v0 = *(const float4*)(vr+0),  v1 = *(const float4*)(vr+4);
            float4 v2 = *(const float4*)(vr+8),  v3 = *(const float4*)(vr+12);
            acc[0]=acc[0]*alpha+p*v0.x; acc[1]=acc[1]*alpha+p*v0.y;
            acc[2]=acc[2]*alpha+p*v0.z; acc[3]=acc[3]*alpha+p*v0.w;
            acc[4]=acc[4]*alpha+p*v1.x; acc[5]=acc[5]*alpha+p*v1.y;
            acc[6]=acc[6]*alpha+p*v1.z; acc[7]=acc[7]*alpha+p*v1.w;
            acc[8]=acc[8]*alpha+p*v2.x; acc[9]=acc[9]*alpha+p*v2.y;
            acc[10]=acc[10]*alpha+p*v2.z; acc[11]=acc[11]*alpha+p*v2.w;
            acc[12]=acc[12]*alpha+p*v3.x; acc[13]=acc[13]*alpha+p*v3.y;
            acc[14]=acc[14]*alpha+p*v3.z; acc[15]=acc[15]*alpha+p*v3.w;
            m = nm;
        }
    }

    #pragma unroll
    for (int mask = 4; mask < 32; mask <<= 1){
        float m2 = __shfl_xor_sync(0xffffffffu, m, mask);
        float l2 = __shfl_xor_sync(0xffffffffu, l, mask);
        float nm = fmaxf(m, m2);
        float a1 = __expf(m - nm), a2 = __expf(m2 - nm);
        l = l*a1 + l2*a2;
        #pragma unroll
        for (int j = 0; j < 16; j++){
            float o = __shfl_xor_sync(0xffffffffu, acc[j], mask);
            acc[j] = acc[j]*a1 + o*a2;
        }
        m = nm;
    }
    if (g == 0){
        float inv = 1.f / l;
        float* yr = Y + (size_t)(b*SS + qi)*DD + h*64 + qd*16;
        #pragma unroll
        for (int j = 0; j < 4; j++){
            float4 o = { acc[j*4]*inv, acc[j*4+1]*inv, acc[j*4+2]*inv, acc[j*4+3]*inv };
            *(float4*)(yr + j*4) = o;
        }
    }
}

// ---------------- orchestration ---------------------------------------------
extern "C" void kernel_launch(void* const* d_in, const int* in_sizes, int n_in,
                              void* d_out, int out_size)
{
    const int*   tokens  = (const int*)  d_in[0];
    const float* tok_emb = (const float*)d_in[1];
    const float* Wq = (const float*)d_in[2];  const float* bq = (const float*)d_in[3];
    const float* Wk = (const float*)d_in[4];  const float* bk = (const float*)d_in[5];
    const float* Wv = (const float*)d_in[6];  const float* bv = (const float*)d_in[7];
    const float* Wo = (const float*)d_in[8];  const float* bo = (const float*)d_in[9];
    const float* ln1g = (const float*)d_in[10]; const float* ln1b = (const float*)d_in[11];
    const float* ln2g = (const float*)d_in[12]; const float* ln2b = (const float*)d_in[13];
    const float* W1 = (const float*)d_in[14]; const float* b1 = (const float*)d_in[15];
    const float* W2 = (const float*)d_in[16]; const float* b2 = (const float*)d_in[17];
    const float* lnfg = (const float*)d_in[18]; const float* lnfb = (const float*)d_in[19];
    const float* fcW = (const float*)d_in[20]; const float* fcb = (const float*)d_in[21];

    float *x, *h, *qkv, *y, *ff, *bqkv, *wt;
    cudaGetSymbolAddress((void**)&x,    g_x);
    cudaGetSymbolAddress((void**)&h,    g_h);
    cudaGetSymbolAddress((void**)&qkv,  g_qkv);
    cudaGetSymbolAddress((void**)&y,    g_y);
    cudaGetSymbolAddress((void**)&ff,   g_ff);
    cudaGetSymbolAddress((void**)&bqkv, g_bqkv);
    cudaGetSymbolAddress((void**)&wt,   g_wt);

    const int SMEM4 = (2*128*36 + 2*32*132) * 4;   // 70656 B
    const int SMEM2 = (2*128*36 + 2*32*68)  * 4;   // 54272 B
    cudaFuncSetAttribute((const void*)mma_gemm<4,1>, cudaFuncAttributeMaxDynamicSharedMemorySize, SMEM4);
    cudaFuncSetAttribute((const void*)mma_gemm<2,2>, cudaFuncAttributeMaxDynamicSharedMemorySize, SMEM2);

    // pre-pass: rounded copies (no transpose needed — B consumed as [K][N])
    pack_qkvw<<<(LL*768*2304/4 + 255)/256, 256>>>(Wq, Wk, Wv, wt + WT_QKV);
    round_copy<<<(LL*589824/4  + 255)/256, 256>>>(Wo, wt + WT_O,  LL*589824/4);
    round_copy<<<(LL*2359296/4 + 255)/256, 256>>>(W1, wt + WT_W1, LL*2359296/4);
    round_copy<<<(LL*2359296/4 + 255)/256, 256>>>(W2, wt + WT_W2, LL*2359296/4);
    round_copy<<<(24576000/4   + 255)/256, 256>>>(fcW, wt + WT_FC, 24576000/4);
    pack_bias<<<(LL*QKVN + 255)/256, 256>>>(bq, bk, bv, bqkv);

    embed_kernel<<<MM, 256>>>(tokens, tok_emb, x);

    for (int l = 0; l < LL; l++){
        ln_kernel<<<MM, 256>>>(x, ln1g + l*DD, ln1b + l*DD, h);
        mma_gemm<4,1><<<dim3(MM/128, QKVN/128), 256, SMEM4>>>(h, wt + WT_QKV + l*WT_QKV_L,
                                                              bqkv + l*QKVN, nullptr, qkv, QKVN, DD, 0);
        attn_kernel<<<BB*HH*(SS/8), 256>>>(qkv, y);
        mma_gemm<2,2><<<dim3(MM/128, DD/64), 256, SMEM2>>>(y, wt + WT_O + l*WT_O_L,
                                                           bo + l*DD, x, x, DD, DD, 0);
        ln_kernel<<<MM, 256>>>(x, ln2g + l*DD, ln2b + l*DD, h);
        mma_gemm<4,1><<<dim3(MM/128, FF/128), 256, SMEM4>>>(h, wt + WT_W1 + l*WT_W1_L,
                                                            b1 + l*FF, nullptr, ff, FF, DD, 1);
        mma_gemm<2,2><<<dim3(MM/128, DD/64), 256, SMEM2>>>(ff, wt + WT_W2 + l*WT_W2_L,
                                                           b2 + l*DD, x, x, DD, FF, 0);
    }
    ln_kernel<<<MM, 256>>>(x, lnfg, lnfb, h);
    mma_gemm<4,1><<<dim3(MM/128, VV/128), 256, SMEM4>>>(h, wt + WT_FC, fcb, nullptr,
                                                        (float*)d_out, VV, DD, 0);
}

// round 12
// speedup vs baseline: 2.1458x; 1.0438x over previous
#include <cuda_runtime.h>
#include <math.h>
#include <stdint.h>

#define BB 2
#define SS 1024
#define DD 768
#define HH 12
#define LL 4
#define VV 32000
#define MM (BB*SS)      // 2048
#define FF (4*DD)       // 3072
#define QKVN (3*DD)     // 2304

// ---------------- scratch (device globals) ----------------------------------
__device__ float g_x  [MM*DD];
__device__ float g_h  [MM*DD];
__device__ float g_qkv[MM*QKVN];
__device__ float g_y  [MM*DD];
__device__ float g_ff [MM*FF];
__device__ float g_bqkv[LL*QKVN];
__device__ float g_wt [52887552];   // tf32-rounded weights, [K][N] layout

#define WT_QKV   0u
#define WT_QKV_L 1769472u           // [768][2304] per layer
#define WT_O     7077888u
#define WT_O_L   589824u            // [768][768]
#define WT_W1    9437184u
#define WT_W1_L  2359296u           // [768][3072]
#define WT_W2    18874368u
#define WT_W2_L  2359296u           // [3072][768]
#define WT_FC    28311552u          // [768][32000]

__device__ __forceinline__ uint32_t f2tf32(float f){
    uint32_t r; asm("cvt.rna.tf32.f32 %0, %1;" : "=r"(r) : "f"(f)); return r;
}
__device__ __forceinline__ float tfr(float f){ return __uint_as_float(f2tf32(f)); }
__device__ __forceinline__ uint32_t smem_u32(const void* p){
    uint32_t r;
    asm("{ .reg .u64 t; cvta.to.shared.u64 t, %1; cvt.u32.u64 %0, t; }" : "=r"(r) : "l"(p));
    return r;
}

#define MMA8(d, a0,a1,a2,a3, b0,b1) \
  asm volatile("mma.sync.aligned.m16n8k8.row.col.f32.tf32.tf32.f32 " \
      "{%0,%1,%2,%3}, {%4,%5,%6,%7}, {%8,%9}, {%0,%1,%2,%3};" \
      : "+f"(d.x),"+f"(d.y),"+f"(d.z),"+f"(d.w) \
      : "r"(__float_as_uint(a0)),"r"(__float_as_uint(a1)), \
        "r"(__float_as_uint(a2)),"r"(__float_as_uint(a3)), \
        "r"(__float_as_uint(b0)),"r"(__float_as_uint(b1)))

#define CP_ASYNC16(dst, src) \
  asm volatile("cp.async.cg.shared.global [%0], [%1], 16;" :: "r"(dst), "l"(src))
#define CP_COMMIT()  asm volatile("cp.async.commit_group;" ::: "memory")
#define CP_WAIT0()   asm volatile("cp.async.wait_group 0;" ::: "memory")

// ---------------- embedding + positional encoding ---------------------------
__global__ void embed_kernel(const int* __restrict__ tokens,
                             const float* __restrict__ tok_emb,
                             float* __restrict__ x)
{
    int row = blockIdx.x;
    int pos = row % SS;
    int tok = tokens[row];
    const float sc = sqrtf((float)DD);
    const float negl = -logf(10000.0f) / (float)DD;
    for (int d = threadIdx.x; d < DD; d += blockDim.x) {
        int i2 = (d >> 1) << 1;
        float div = __expf((float)i2 * negl);
        float ang = (float)pos * div;
        float pe = (d & 1) ? cosf(ang) : sinf(ang);
        x[(size_t)row*DD + d] = tok_emb[(size_t)tok*DD + d] * sc + pe;
    }
}

// ---------------- layernorm --------------------------------------------------
__global__ void __launch_bounds__(256) ln_kernel(const float* __restrict__ X,
                                                 const float* __restrict__ g,
                                                 const float* __restrict__ b,
                                                 float* __restrict__ O)
{
    __shared__ float red[8];
    __shared__ float s_mean, s_rstd;
    int row = blockIdx.x, tid = threadIdx.x;
    const float* xr = X + (size_t)row*DD;
    float v0 = xr[tid], v1 = xr[tid+256], v2 = xr[tid+512];
    float s = v0 + v1 + v2;
    #pragma unroll
    for (int o = 16; o; o >>= 1) s += __shfl_xor_sync(0xffffffffu, s, o);
    if ((tid & 31) == 0) red[tid >> 5] = s;
    __syncthreads();
    if (tid == 0) {
        float t = 0.f;
        #pragma unroll
        for (int i = 0; i < 8; i++) t += red[i];
        s_mean = t / (float)DD;
    }
    __syncthreads();
    float mu = s_mean;
    float d0 = v0-mu, d1 = v1-mu, d2 = v2-mu;
    s = d0*d0 + d1*d1 + d2*d2;
    #pragma unroll
    for (int o = 16; o; o >>= 1) s += __shfl_xor_sync(0xffffffffu, s, o);
    if ((tid & 31) == 0) red[tid >> 5] = s;
    __syncthreads();
    if (tid == 0) {
        float t = 0.f;
        #pragma unroll
        for (int i = 0; i < 8; i++) t += red[i];
        s_rstd = rsqrtf(t / (float)DD + 1e-5f);
    }
    __syncthreads();
    float r = s_rstd;
    size_t base = (size_t)row*DD;
    O[base+tid    ] = d0*r*g[tid    ] + b[tid    ];
    O[base+tid+256] = d1*r*g[tid+256] + b[tid+256];
    O[base+tid+512] = d2*r*g[tid+512] + b[tid+512];
}

// ---------------- pre-pass: coalesced tf32 round copies ----------------------
__global__ void round_copy(const float* __restrict__ in, float* __restrict__ out, int n4)
{
    int i = blockIdx.x*256 + threadIdx.x;
    if (i < n4){
        float4 v = ((const float4*)in)[i];
        ((float4*)out)[i] = make_float4(tfr(v.x), tfr(v.y), tfr(v.z), tfr(v.w));
    }
}

// build fused [768][2304] = [Wq | Wk | Wv] per layer (tf32-rounded), [K][N]
__global__ void pack_qkvw(const float* __restrict__ Wq, const float* __restrict__ Wk,
                          const float* __restrict__ Wv, float* __restrict__ out)
{
    int i = blockIdx.x*256 + threadIdx.x;           // float4 index
    const int total4 = LL*768*2304/4;
    if (i >= total4) return;
    int n4 = i % 576;                               // 2304/4
    int lk = i / 576;                               // l*768 + k
    int sel = n4 / 192;                             // which of q/k/v
    int n4s = n4 - sel*192;
    const float* src = (sel == 0) ? Wq : (sel == 1) ? Wk : Wv;
    float4 v = ((const float4*)src)[(size_t)lk*192 + n4s];
    ((float4*)out)[i] = make_float4(tfr(v.x), tfr(v.y), tfr(v.z), tfr(v.w));
}

// ---------------- qkv bias concat --------------------------------------------
__global__ void pack_bias(const float* __restrict__ bq, const float* __restrict__ bk,
                          const float* __restrict__ bv, float* __restrict__ out)
{
    int i = blockIdx.x*256 + threadIdx.x;
    if (i >= LL*QKVN) return;
    int l = i / QKVN, n = i % QKVN;
    float v = (n < 768) ? bq[l*768 + n]
            : (n < 1536) ? bk[l*768 + n - 768]
                         : bv[l*768 + n - 1536];
    out[i] = v;
}

// ---------------- tf32 mma.sync GEMM, B native [K][N] via cp.async -----------
// C[2048, N] = act(A[2048,K] @ B[K,N] + bias [+ res])
// CTA tile 128 x (32*WNT), BK=32, 8 warps (2m x 4n), warp tile 64 x (8*WNT).
// A: register-staged +tf32 round, k-permuted SMEM (c = 8*(k%4)+k/4, pitch 36):
//    LDS.128 fragment loads, conflict-free (bank-quad = (2g + t'... verified)).
// B: cp.async into [k][n] SMEM, pitch BN+8 (== 8 mod 32 -> bank = 8t+g, bijective
//    over the warp: conflict-free LDS.32 fragment reads).
// MINB=2 -> ptxas caps regs at 128 -> 2 CTAs/SM: cross-CTA overlap of the
// per-chunk sync/cp.async-wait stalls (the R10 limiter at occupancy 1).
template<int WNT, int MINB>
__global__ void __launch_bounds__(256, MINB) mma_gemm(
    const float* __restrict__ A, const float* __restrict__ B,
    const float* __restrict__ bias, const float* __restrict__ res,
    float* __restrict__ C, int N, int K, int act)
{
    const int BN  = 32*WNT;
    const int BNP = BN + 8;                // == 8 (mod 32): conflict-free B reads
    extern __shared__ float sm[];
    float* As = sm;                        // 2 * 128*36
    float* Bs = sm + 2*128*36;             // 2 * 32*BNP
    uint32_t uBs = smem_u32(Bs);

    int tid = threadIdx.x;
    int wid = tid >> 5, lane = tid & 31;
    int g = lane >> 2, t = lane & 3;
    int wm = wid & 1, wn = wid >> 1;
    int bm = blockIdx.x * 128, bn = blockIdx.y * BN;

    int srow = tid >> 3, scol = tid & 7;
    const float* Abase = A + (size_t)(bm + srow)*K + scol*4;

    float4 ra[4];
    float4 acc[4][WNT];
    #pragma unroll
    for (int i = 0; i < 4; i++)
        #pragma unroll
        for (int j = 0; j < WNT; j++)
            acc[i][j] = make_float4(0.f,0.f,0.f,0.f);

    auto ldA = [&](int kt){
        const float* Ak = Abase + (size_t)kt*32;
        #pragma unroll
        for (int i = 0; i < 4; i++) ra[i] = *(const float4*)(Ak + (size_t)(32*i)*K);
    };
    auto stA = [&](int buf){
        float* dA = As + buf*(128*36);
        #pragma unroll
        for (int i = 0; i < 4; i++){
            float* p = dA + (srow + 32*i)*36 + scol;
            p[0]=tfr(ra[i].x); p[8]=tfr(ra[i].y); p[16]=tfr(ra[i].z); p[24]=tfr(ra[i].w);
        }
    };
    auto cpB = [&](int kt, int buf){
        const float* Bg = B + (size_t)kt*32*N + bn;
        uint32_t dst = uBs + buf*(32*BNP*4);
        if (WNT == 4){
            int row = tid >> 5, ch = tid & 31;
            #pragma unroll
            for (int i = 0; i < 4; i++){
                uint32_t d = dst + (uint32_t)(((row + 8*i)*BNP + ch*4)*4);
                const float* s = Bg + (size_t)(row + 8*i)*N + ch*4;
                CP_ASYNC16(d, s);
            }
        } else {
            int row = tid >> 4, ch = tid & 15;
            #pragma unroll
            for (int i = 0; i < 2; i++){
                uint32_t d = dst + (uint32_t)(((row + 16*i)*BNP + ch*4)*4);
                const float* s = Bg + (size_t)(row + 16*i)*N + ch*4;
                CP_ASYNC16(d, s);
            }
        }
        CP_COMMIT();
    };

    cpB(0, 0); ldA(0); stA(0);
    CP_WAIT0();
    __syncthreads();

    const int NK = K / 32;
    for (int kt = 0; kt < NK; kt++){
        int cur = kt & 1;
        if (kt + 1 < NK){ cpB(kt+1, cur^1); ldA(kt+1); }
        const float* Ac = As + cur*(128*36);
        const float* Bc = Bs + cur*(32*BNP);
        #pragma unroll
        for (int j = 0; j < 2; j++){
            float4 alo[4], ahi[4];
            #pragma unroll
            for (int mt = 0; mt < 4; mt++){
                int r = wm*64 + mt*16 + g;
                alo[mt] = *(const float4*)(Ac + r*36 + t*8 + 4*j);
                ahi[mt] = *(const float4*)(Ac + (r+8)*36 + t*8 + 4*j);
            }
            #pragma unroll
            for (int nt = 0; nt < WNT; nt++){
                int n = wn*(8*WNT) + nt*8 + g;
                float b0 = Bc[(16*j + t     )*BNP + n];
                float b1 = Bc[(16*j + t + 4 )*BNP + n];
                float b2 = Bc[(16*j + t + 8 )*BNP + n];
                float b3 = Bc[(16*j + t + 12)*BNP + n];
                #pragma unroll
                for (int mt = 0; mt < 4; mt++){
                    MMA8(acc[mt][nt], alo[mt].x, ahi[mt].x, alo[mt].y, ahi[mt].y, b0, b1);
                    MMA8(acc[mt][nt], alo[mt].z, ahi[mt].z, alo[mt].w, ahi[mt].w, b2, b3);
                }
            }
        }
        if (kt + 1 < NK){
            stA(cur^1);
            CP_WAIT0();
            __syncthreads();
        }
    }

    // epilogue: direct STG with bias/res/act
    #pragma unroll
    for (int mt = 0; mt < 4; mt++){
        int r0 = bm + wm*64 + mt*16 + g;
        #pragma unroll
        for (int nt = 0; nt < WNT; nt++){
            int col = bn + wn*(8*WNT) + nt*8 + 2*t;
            float b0 = bias[col], b1 = bias[col+1];
            float4 c = acc[mt][nt];
            float v0 = c.x + b0, v1 = c.y + b1;
            float w0 = c.z + b0, w1 = c.w + b1;
            if (res){
                v0 += res[(size_t)r0*N + col];     v1 += res[(size_t)r0*N + col + 1];
                w0 += res[(size_t)(r0+8)*N + col]; w1 += res[(size_t)(r0+8)*N + col + 1];
            }
            if (act){
                v0 = 0.5f*v0*(1.0f + erff(v0*0.70710678118654752f));
                v1 = 0.5f*v1*(1.0f + erff(v1*0.70710678118654752f));
                w0 = 0.5f*w0*(1.0f + erff(w0*0.70710678118654752f));
                w1 = 0.5f*w1*(1.0f + erff(w1*0.70710678118654752f));
            }
            *(float2*)(C + (size_t)r0*N + col)     = make_float2(v0, v1);
            *(float2*)(C + (size_t)(r0+8)*N + col) = make_float2(w0, w1);
        }
    }
}

// ---------------- attention: warp/query, 8 keys/iter, group-local softmax ----
// QKV layout [B*S, 2304]: q at +0, k at +768, v at +1536 (head h at +h*64)
__global__ void __launch_bounds__(256) attn_kernel(const float* __restrict__ QKV,
                                                   float* __restrict__ Y)
{
    int wid = threadIdx.x >> 5, lane = threadIdx.x & 31;
    int g  = lane >> 2;
    int qd = lane & 3;
    int blk  = blockIdx.x;
    int qblk = blk & 127;
    int bh   = blk >> 7;
    int h = bh % HH, b = bh / HH;
    int qi = qblk*8 + wid;

    const float* qr = QKV + (size_t)(b*SS + qi)*QKVN + h*64 + qd*16;
    float4 q0 = *(const float4*)(qr+0),  q1 = *(const float4*)(qr+4);
    float4 q2 = *(const float4*)(qr+8),  q3 = *(const float4*)(qr+12);
    const float s8 = 0.125f;
    q0.x*=s8;q0.y*=s8;q0.z*=s8;q0.w*=s8; q1.x*=s8;q1.y*=s8;q1.z*=s8;q1.w*=s8;
    q2.x*=s8;q2.y*=s8;q2.z*=s8;q2.w*=s8; q3.x*=s8;q3.y*=s8;q3.z*=s8;q3.w*=s8;

    const float* Kb = QKV + (size_t)b*SS*QKVN + 768  + h*64 + qd*16;
    const float* Vb = QKV + (size_t)b*SS*QKVN + 1536 + h*64 + qd*16;

    float m = -1e30f, l = 0.f;
    float acc[16];
    #pragma unroll
    for (int j = 0; j < 16; j++) acc[j] = 0.f;

    int nit = (qi >> 3) + 1;
    for (int it = 0; it < nit; it++){
        int s = it*8 + g;
        const float* kr = Kb + (size_t)s*QKVN;
        float4 k0 = *(const float4*)(kr+0),  k1 = *(const float4*)(kr+4);
        float4 k2 = *(const float4*)(kr+8),  k3 = *(const float4*)(kr+12);
        float ss = q0.x*k0.x + q0.y*k0.y + q0.z*k0.z + q0.w*k0.w
                 + q1.x*k1.x + q1.y*k1.y + q1.z*k1.z + q1.w*k1.w
                 + q2.x*k2.x + q2.y*k2.y + q2.z*k2.z + q2.w*k2.w
                 + q3.x*k3.x + q3.y*k3.y + q3.z*k3.z + q3.w*k3.w;
        ss += __shfl_xor_sync(0xffffffffu, ss, 1);
        ss += __shfl_xor_sync(0xffffffffu, ss, 2);
        if (s <= qi){
            float nm = fmaxf(m, ss);
            float alpha = __expf(m - nm);
            float p = __expf(ss - nm);
            l = l*alpha + p;
            const float* vr = Vb + (size_t)s*QKVN;
            float4 v0 = *(const float4*)(vr+0),  v1 = *(const float4*)(vr+4);
            float4 v2 = *(const float4*)(vr+8),  v3 = *(const float4*)(vr+12);
            acc[0]=acc[0]*alpha+p*v0.x; acc[1]=acc[1]*alpha+p*v0.y;
            acc[2]=acc[2]*alpha+p*v0.z; acc[3]=acc[3]*alpha+p*v0.w;
            acc[4]=acc[4]*alpha+p*v1.x; acc[5]=acc[5]*alpha+p*v1.y;
            acc[6]=acc[6]*alpha+p*v1.z; acc[7]=acc[7]*alpha+p*v1.w;
            acc[8]=acc[8]*alpha+p*v2.x; acc[9]=acc[9]*alpha+p*v2.y;
            acc[10]=acc[10]*alpha+p*v2.z; acc[11]=acc[11]*alpha+p*v2.w;
            acc[12]=acc[12]*alpha+p*v3.x; acc[13]=acc[13]*alpha+p*v3.y;
            acc[14]=acc[14]*alpha+p*v3.z; acc[15]=acc[15]*alpha+p*v3.w;
            m = nm;
        }
    }

    #pragma unroll
    for (int mask = 4; mask < 32; mask <<= 1){
        float m2 = __shfl_xor_sync(0xffffffffu, m, mask);
        float l2 = __shfl_xor_sync(0xffffffffu, l, mask);
        float nm = fmaxf(m, m2);
        float a1 = __expf(m - nm), a2 = __expf(m2 - nm);
        l = l*a1 + l2*a2;
        #pragma unroll
        for (int j = 0; j < 16; j++){
            float o = __shfl_xor_sync(0xffffffffu, acc[j], mask);
            acc[j] = acc[j]*a1 + o*a2;
        }
        m = nm;
    }
    if (g == 0){
        float inv = 1.f / l;
        float* yr = Y + (size_t)(b*SS + qi)*DD + h*64 + qd*16;
        #pragma unroll
        for (int j = 0; j < 4; j++){
            float4 o = { acc[j*4]*inv, acc[j*4+1]*inv, acc[j*4+2]*inv, acc[j*4+3]*inv };
            *(float4*)(yr + j*4) = o;
        }
    }
}

// ---------------- orchestration ---------------------------------------------
extern "C" void kernel_launch(void* const* d_in, const int* in_sizes, int n_in,
                              void* d_out, int out_size)
{
    const int*   tokens  = (const int*)  d_in[0];
    const float* tok_emb = (const float*)d_in[1];
    const float* Wq = (const float*)d_in[2];  const float* bq = (const float*)d_in[3];
    const float* Wk = (const float*)d_in[4];  const float* bk = (const float*)d_in[5];
    const float* Wv = (const float*)d_in[6];  const float* bv = (const float*)d_in[7];
    const float* Wo = (const float*)d_in[8];  const float* bo = (const float*)d_in[9];
    const float* ln1g = (const float*)d_in[10]; const float* ln1b = (const float*)d_in[11];
    const float* ln2g = (const float*)d_in[12]; const float* ln2b = (const float*)d_in[13];
    const float* W1 = (const float*)d_in[14]; const float* b1 = (const float*)d_in[15];
    const float* W2 = (const float*)d_in[16]; const float* b2 = (const float*)d_in[17];
    const float* lnfg = (const float*)d_in[18]; const float* lnfb = (const float*)d_in[19];
    const float* fcW = (const float*)d_in[20]; const float* fcb = (const float*)d_in[21];

    float *x, *h, *qkv, *y, *ff, *bqkv, *wt;
    cudaGetSymbolAddress((void**)&x,    g_x);
    cudaGetSymbolAddress((void**)&h,    g_h);
    cudaGetSymbolAddress((void**)&qkv,  g_qkv);
    cudaGetSymbolAddress((void**)&y,    g_y);
    cudaGetSymbolAddress((void**)&ff,   g_ff);
    cudaGetSymbolAddress((void**)&bqkv, g_bqkv);
    cudaGetSymbolAddress((void**)&wt,   g_wt);

    const int SMEM4 = (2*128*36 + 2*32*136) * 4;   // 71680 B  (2 CTA/SM: 143KB)
    const int SMEM2 = (2*128*36 + 2*32*72)  * 4;   // 55296 B  (2 CTA/SM: 110KB)
    cudaFuncSetAttribute((const void*)mma_gemm<4,2>, cudaFuncAttributeMaxDynamicSharedMemorySize, SMEM4);
    cudaFuncSetAttribute((const void*)mma_gemm<2,2>, cudaFuncAttributeMaxDynamicSharedMemorySize, SMEM2);

    // pre-pass: rounded copies (no transpose needed — B consumed as [K][N])
    pack_qkvw<<<(LL*768*2304/4 + 255)/256, 256>>>(Wq, Wk, Wv, wt + WT_QKV);
    round_copy<<<(LL*589824/4  + 255)/256, 256>>>(Wo, wt + WT_O,  LL*589824/4);
    round_copy<<<(LL*2359296/4 + 255)/256, 256>>>(W1, wt + WT_W1, LL*2359296/4);
    round_copy<<<(LL*2359296/4 + 255)/256, 256>>>(W2, wt + WT_W2, LL*2359296/4);
    round_copy<<<(24576000/4   + 255)/256, 256>>>(fcW, wt + WT_FC, 24576000/4);
    pack_bias<<<(LL*QKVN + 255)/256, 256>>>(bq, bk, bv, bqkv);

    embed_kernel<<<MM, 256>>>(tokens, tok_emb, x);

    for (int l = 0; l < LL; l++){
        ln_kernel<<<MM, 256>>>(x, ln1g + l*DD, ln1b + l*DD, h);
        mma_gemm<4,2><<<dim3(MM/128, QKVN/128), 256, SMEM4>>>(h, wt + WT_QKV + l*WT_QKV_L,
                                                              bqkv + l*QKVN, nullptr, qkv, QKVN, DD, 0);
        attn_kernel<<<BB*HH*(SS/8), 256>>>(qkv, y);
        mma_gemm<2,2><<<dim3(MM/128, DD/64), 256, SMEM2>>>(y, wt + WT_O + l*WT_O_L,
                                                           bo + l*DD, x, x, DD, DD, 0);
        ln_kernel<<<MM, 256>>>(x, ln2g + l*DD, ln2b + l*DD, h);
        mma_gemm<4,2><<<dim3(MM/128, FF/128), 256, SMEM4>>>(h, wt + WT_W1 + l*WT_W1_L,
                                                            b1 + l*FF, nullptr, ff, FF, DD, 1);
        mma_gemm<2,2><<<dim3(MM/128, DD/64), 256, SMEM2>>>(ff, wt + WT_W2 + l*WT_W2_L,
                                                           b2 + l*DD, x, x, DD, FF, 0);
    }
    ln_kernel<<<MM, 256>>>(x, lnfg, lnfb, h);
    mma_gemm<4,2><<<dim3(MM/128, VV/128), 256, SMEM4>>>(h, wt + WT_FC, fcb, nullptr,
                                                        (float*)d_out, VV, DD, 0);
}

// round 13
// speedup vs baseline: 2.2004x; 1.0255x over previous
#include <cuda_runtime.h>
#include <math.h>
#include <stdint.h>

#define BB 2
#define SS 1024
#define DD 768
#define HH 12
#define LL 4
#define VV 32000
#define MM (BB*SS)      // 2048
#define FF (4*DD)       // 3072
#define QKVN (3*DD)     // 2304

// ---------------- scratch (device globals) ----------------------------------
__device__ float g_x  [MM*DD];
__device__ float g_h  [MM*DD];    // tf32-rounded (GEMM A input)
__device__ float g_qkv[MM*QKVN];
__device__ float g_y  [MM*DD];    // tf32-rounded
__device__ float g_ff [MM*FF];    // tf32-rounded
__device__ float g_bqkv[LL*QKVN];
__device__ float g_wt [52887552]; // tf32-rounded weights, [K][N] layout

#define WT_QKV   0u
#define WT_QKV_L 1769472u
#define WT_O     7077888u
#define WT_O_L   589824u
#define WT_W1    9437184u
#define WT_W1_L  2359296u
#define WT_W2    18874368u
#define WT_W2_L  2359296u
#define WT_FC    28311552u

__device__ __forceinline__ uint32_t f2tf32(float f){
    uint32_t r; asm("cvt.rna.tf32.f32 %0, %1;" : "=r"(r) : "f"(f)); return r;
}
__device__ __forceinline__ float tfr(float f){ return __uint_as_float(f2tf32(f)); }
__device__ __forceinline__ uint32_t smem_u32(const void* p){
    uint32_t r;
    asm("{ .reg .u64 t; cvta.to.shared.u64 t, %1; cvt.u32.u64 %0, t; }" : "=r"(r) : "l"(p));
    return r;
}

#define MMA8(d, a0,a1,a2,a3, b0,b1) \
  asm volatile("mma.sync.aligned.m16n8k8.row.col.f32.tf32.tf32.f32 " \
      "{%0,%1,%2,%3}, {%4,%5,%6,%7}, {%8,%9}, {%0,%1,%2,%3};" \
      : "+f"(d.x),"+f"(d.y),"+f"(d.z),"+f"(d.w) \
      : "r"(__float_as_uint(a0)),"r"(__float_as_uint(a1)), \
        "r"(__float_as_uint(a2)),"r"(__float_as_uint(a3)), \
        "r"(__float_as_uint(b0)),"r"(__float_as_uint(b1)))

#define CP_ASYNC16(dst, src) \
  asm volatile("cp.async.cg.shared.global [%0], [%1], 16;" :: "r"(dst), "l"(src))
#define CP_COMMIT()  asm volatile("cp.async.commit_group;" ::: "memory")
#define CP_WAIT1()   asm volatile("cp.async.wait_group 1;" ::: "memory")

// ---------------- embedding + positional encoding ---------------------------
__global__ void embed_kernel(const int* __restrict__ tokens,
                             const float* __restrict__ tok_emb,
                             float* __restrict__ x)
{
    int row = blockIdx.x;
    int pos = row % SS;
    int tok = tokens[row];
    const float sc = sqrtf((float)DD);
    const float negl = -logf(10000.0f) / (float)DD;
    for (int d = threadIdx.x; d < DD; d += blockDim.x) {
        int i2 = (d >> 1) << 1;
        float div = __expf((float)i2 * negl);
        float ang = (float)pos * div;
        float pe = (d & 1) ? cosf(ang) : sinf(ang);
        x[(size_t)row*DD + d] = tok_emb[(size_t)tok*DD + d] * sc + pe;
    }
}

// ---------------- layernorm (writes tf32-rounded output) ---------------------
__global__ void __launch_bounds__(256) ln_kernel(const float* __restrict__ X,
                                                 const float* __restrict__ g,
                                                 const float* __restrict__ b,
                                                 float* __restrict__ O)
{
    __shared__ float red[8];
    __shared__ float s_mean, s_rstd;
    int row = blockIdx.x, tid = threadIdx.x;
    const float* xr = X + (size_t)row*DD;
    float v0 = xr[tid], v1 = xr[tid+256], v2 = xr[tid+512];
    float s = v0 + v1 + v2;
    #pragma unroll
    for (int o = 16; o; o >>= 1) s += __shfl_xor_sync(0xffffffffu, s, o);
    if ((tid & 31) == 0) red[tid >> 5] = s;
    __syncthreads();
    if (tid == 0) {
        float t = 0.f;
        #pragma unroll
        for (int i = 0; i < 8; i++) t += red[i];
        s_mean = t / (float)DD;
    }
    __syncthreads();
    float mu = s_mean;
    float d0 = v0-mu, d1 = v1-mu, d2 = v2-mu;
    s = d0*d0 + d1*d1 + d2*d2;
    #pragma unroll
    for (int o = 16; o; o >>= 1) s += __shfl_xor_sync(0xffffffffu, s, o);
    if ((tid & 31) == 0) red[tid >> 5] = s;
    __syncthreads();
    if (tid == 0) {
        float t = 0.f;
        #pragma unroll
        for (int i = 0; i < 8; i++) t += red[i];
        s_rstd = rsqrtf(t / (float)DD + 1e-5f);
    }
    __syncthreads();
    float r = s_rstd;
    size_t base = (size_t)row*DD;
    O[base+tid    ] = tfr(d0*r*g[tid    ] + b[tid    ]);
    O[base+tid+256] = tfr(d1*r*g[tid+256] + b[tid+256]);
    O[base+tid+512] = tfr(d2*r*g[tid+512] + b[tid+512]);
}

// ---------------- pre-pass: coalesced tf32 round copies ----------------------
__global__ void round_copy(const float* __restrict__ in, float* __restrict__ out, int n4)
{
    int i = blockIdx.x*256 + threadIdx.x;
    if (i < n4){
        float4 v = ((const float4*)in)[i];
        ((float4*)out)[i] = make_float4(tfr(v.x), tfr(v.y), tfr(v.z), tfr(v.w));
    }
}

__global__ void pack_qkvw(const float* __restrict__ Wq, const float* __restrict__ Wk,
                          const float* __restrict__ Wv, float* __restrict__ out)
{
    int i = blockIdx.x*256 + threadIdx.x;
    const int total4 = LL*768*2304/4;
    if (i >= total4) return;
    int n4 = i % 576;
    int lk = i / 576;
    int sel = n4 / 192;
    int n4s = n4 - sel*192;
    const float* src = (sel == 0) ? Wq : (sel == 1) ? Wk : Wv;
    float4 v = ((const float4*)src)[(size_t)lk*192 + n4s];
    ((float4*)out)[i] = make_float4(tfr(v.x), tfr(v.y), tfr(v.z), tfr(v.w));
}

__global__ void pack_bias(const float* __restrict__ bq, const float* __restrict__ bk,
                          const float* __restrict__ bv, float* __restrict__ out)
{
    int i = blockIdx.x*256 + threadIdx.x;
    if (i >= LL*QKVN) return;
    int l = i / QKVN, n = i % QKVN;
    float v = (n < 768) ? bq[l*768 + n]
            : (n < 1536) ? bk[l*768 + n - 768]
                         : bv[l*768 + n - 1536];
    out[i] = v;
}

// ---------------- tf32 mma.sync GEMM, 3-stage cp.async for A and B -----------
// C[2048, N] = act(A[2048,K] @ B[K,N] + bias [+ res]); A pre-rounded tf32.
// CTA tile 128 x (32*WNT), BK=32, 8 warps (2m x 4n), warp tile 64 x (8*WNT).
// A SMEM: [row][32] pitch 32, 16B chunks XOR-swizzled (c ^= row&7):
//   cp.async-writable, fragment LDS.32 bank = 4*(c^g)+t -> conflict-free.
// B SMEM: [k][n] pitch BN+8 (== 8 mod 32): fragment bank = 8t+g -> conflict-free.
// One __syncthreads per chunk; prefetch distance 2 chunks.
template<int WNT, int MINB>
__global__ void __launch_bounds__(256, MINB) mma_gemm(
    const float* __restrict__ A, const float* __restrict__ B,
    const float* __restrict__ bias, const float* __restrict__ res,
    float* __restrict__ C, int N, int K, int act)
{
    const int BN   = 32*WNT;
    const int BNP  = BN + 8;
    const int ASTG = 128*32;            // floats per A stage
    const int BSTG = 32*BNP;            // floats per B stage
    extern __shared__ float sm[];
    float* As = sm;                      // 3 * ASTG
    float* Bs = sm + 3*ASTG;             // 3 * BSTG
    uint32_t uAs = smem_u32(As);
    uint32_t uBs = smem_u32(Bs);

    int tid = threadIdx.x;
    int wid = tid >> 5, lane = tid & 31;
    int g = lane >> 2, t = lane & 3;
    int wm = wid & 1, wn = wid >> 1;
    int bm = blockIdx.x * 128, bn = blockIdx.y * BN;

    float4 acc[4][WNT];
    #pragma unroll
    for (int i = 0; i < 4; i++)
        #pragma unroll
        for (int j = 0; j < WNT; j++)
            acc[i][j] = make_float4(0.f,0.f,0.f,0.f);

    // A copy: 128 rows x 8 chunks(16B); thread -> row=tid>>1, chunks (tid&1)*4 + 0..3
    int arow = tid >> 1, acb = (tid & 1) * 4;
    const float* Agb = A + (size_t)(bm + arow)*K;
    auto cpA = [&](int kt, int stg){
        const float* srcp = Agb + kt*32;
        uint32_t dst = uAs + stg*(ASTG*4) + arow*128;
        #pragma unroll
        for (int cc = 0; cc < 4; cc++){
            int c = acb + cc;
            CP_ASYNC16(dst + ((c ^ (arow & 7)) << 4), srcp + c*4);
        }
    };
    auto cpB = [&](int kt, int stg){
        const float* Bg = B + (size_t)kt*32*N + bn;
        uint32_t dst = uBs + stg*(BSTG*4);
        if (WNT == 4){
            int row = tid >> 5, ch = tid & 31;
            #pragma unroll
            for (int i = 0; i < 4; i++){
                CP_ASYNC16(dst + (uint32_t)(((row + 8*i)*BNP + ch*4)*4),
                           Bg + (size_t)(row + 8*i)*N + ch*4);
            }
        } else {
            int row = tid >> 4, ch = tid & 15;
            #pragma unroll
            for (int i = 0; i < 2; i++){
                CP_ASYNC16(dst + (uint32_t)(((row + 16*i)*BNP + ch*4)*4),
                           Bg + (size_t)(row + 16*i)*N + ch*4);
            }
        }
    };

    cpA(0, 0); cpB(0, 0); CP_COMMIT();
    cpA(1, 1); cpB(1, 1); CP_COMMIT();

    const int NK = K / 32;
    int stg = 0;
    for (int kt = 0; kt < NK; kt++){
        CP_WAIT1();                  // stage kt's copies complete
        __syncthreads();             // all warps done with stage (kt-1) too
        int pf = kt + 2;
        if (pf < NK){
            int pstg = stg - 1; if (pstg < 0) pstg = 2;
            cpA(pf, pstg); cpB(pf, pstg);
        }
        CP_COMMIT();                 // (possibly empty) keeps group count advancing

        const float* Ac = As + stg*ASTG;
        const float* Bc = Bs + stg*BSTG;
        #pragma unroll
        for (int j = 0; j < 4; j++){             // k = 8j .. 8j+7
            int sw0 = (((2*j    ) ^ g) << 2) + t;
            int sw1 = (((2*j + 1) ^ g) << 2) + t;
            float a[4][4];
            #pragma unroll
            for (int mt = 0; mt < 4; mt++){
                int r0 = wm*64 + mt*16 + g;
                a[mt][0] = Ac[ r0     *32 + sw0];
                a[mt][1] = Ac[(r0 + 8)*32 + sw0];
                a[mt][2] = Ac[ r0     *32 + sw1];
                a[mt][3] = Ac[(r0 + 8)*32 + sw1];
            }
            float bf[WNT][2];
            #pragma unroll
            for (int nt = 0; nt < WNT; nt++){
                int nn = wn*(8*WNT) + nt*8 + g;
                bf[nt][0] = Bc[(8*j + t    )*BNP + nn];
                bf[nt][1] = Bc[(8*j + t + 4)*BNP + nn];
            }
            #pragma unroll
            for (int mt = 0; mt < 4; mt++)
                #pragma unroll
                for (int nt = 0; nt < WNT; nt++)
                    MMA8(acc[mt][nt], a[mt][0], a[mt][1], a[mt][2], a[mt][3],
                         bf[nt][0], bf[nt][1]);
        }
        stg++; if (stg == 3) stg = 0;
    }

    // epilogue: direct STG with bias/res/act (act output tf32-rounded: W2 input)
    #pragma unroll
    for (int mt = 0; mt < 4; mt++){
        int r0 = bm + wm*64 + mt*16 + g;
        #pragma unroll
        for (int nt = 0; nt < WNT; nt++){
            int col = bn + wn*(8*WNT) + nt*8 + 2*t;
            float b0 = bias[col], b1 = bias[col+1];
            float4 c = acc[mt][nt];
            float v0 = c.x + b0, v1 = c.y + b1;
            float w0 = c.z + b0, w1 = c.w + b1;
            if (res){
                v0 += res[(size_t)r0*N + col];     v1 += res[(size_t)r0*N + col + 1];
                w0 += res[(size_t)(r0+8)*N + col]; w1 += res[(size_t)(r0+8)*N + col + 1];
            }
            if (act){
                v0 = tfr(0.5f*v0*(1.0f + erff(v0*0.70710678118654752f)));
                v1 = tfr(0.5f*v1*(1.0f + erff(v1*0.70710678118654752f)));
                w0 = tfr(0.5f*w0*(1.0f + erff(w0*0.70710678118654752f)));
                w1 = tfr(0.5f*w1*(1.0f + erff(w1*0.70710678118654752f)));
            }
            *(float2*)(C + (size_t)r0*N + col)     = make_float2(v0, v1);
            *(float2*)(C + (size_t)(r0+8)*N + col) = make_float2(w0, w1);
        }
    }
}

// ---------------- attention (writes tf32-rounded y) --------------------------
__global__ void __launch_bounds__(256) attn_kernel(const float* __restrict__ QKV,
                                                   float* __restrict__ Y)
{
    int wid = threadIdx.x >> 5, lane = threadIdx.x & 31;
    int g  = lane >> 2;
    int qd = lane & 3;
    int blk  = blockIdx.x;
    int qblk = blk & 127;
    int bh   = blk >> 7;
    int h = bh % HH, b = bh / HH;
    int qi = qblk*8 + wid;

    const float* qr = QKV + (size_t)(b*SS + qi)*QKVN + h*64 + qd*16;
    float4 q0 = *(const float4*)(qr+0),  q1 = *(const float4*)(qr+4);
    float4 q2 = *(const float4*)(qr+8),  q3 = *(const float4*)(qr+12);
    const float s8 = 0.125f;
    q0.x*=s8;q0.y*=s8;q0.z*=s8;q0.w*=s8; q1.x*=s8;q1.y*=s8;q1.z*=s8;q1.w*=s8;
    q2.x*=s8;q2.y*=s8;q2.z*=s8;q2.w*=s8; q3.x*=s8;q3.y*=s8;q3.z*=s8;q3.w*=s8;

    const float* Kb = QKV + (size_t)b*SS*QKVN + 768  + h*64 + qd*16;
    const float* Vb = QKV + (size_t)b*SS*QKVN + 1536 + h*64 + qd*16;

    float m = -1e30f, l = 0.f;
    float acc[16];
    #pragma unroll
    for (int j = 0; j < 16; j++) acc[j] = 0.f;

    int nit = (qi >> 3) + 1;
    for (int it = 0; it < nit; it++){
        int s = it*8 + g;
        const float* kr = Kb + (size_t)s*QKVN;
        float4 k0 = *(const float4*)(kr+0),  k1 = *(const float4*)(kr+4);
        float4 k2 = *(const float4*)(kr+8),  k3 = *(const float4*)(kr+12);
        float ss = q0.x*k0.x + q0.y*k0.y + q0.z*k0.z + q0.w*k0.w
                 + q1.x*k1.x + q1.y*k1.y + q1.z*k1.z + q1.w*k1.w
                 + q2.x*k2.x + q2.y*k2.y + q2.z*k2.z + q2.w*k2.w
                 + q3.x*k3.x + q3.y*k3.y + q3.z*k3.z + q3.w*k3.w;
        ss += __shfl_xor_sync(0xffffffffu, ss, 1);
        ss += __shfl_xor_sync(0xffffffffu, ss, 2);
        if (s <= qi){
            float nm = fmaxf(m, ss);
            float alpha = __expf(m - nm);
            float p = __expf(ss - nm);
            l = l*alpha + p;
            const float* vr = Vb + (size_t)s*QKVN;
            float4 v0 = *(const float4*)(vr+0),  v1 = *(const float4*)(vr+4);
            float4 v2 = *(const float4*)(vr+8),  v3 = *(const float4*)(vr+12);
            acc[0]=acc[0]*alpha+p*v0.x; acc[1]=acc[1]*alpha+p*v0.y;
            acc[2]=acc[2]*alpha+p*v0.z; acc[3]=acc[3]*alpha+p*v0.w;
            acc[4]=acc[4]*alpha+p*v1.x; acc[5]=acc[5]*alpha+p*v1.y;
            acc[6]=acc[6]*alpha+p*v1.z; acc[7]=acc[7]*alpha+p*v1.w;
            acc[8]=acc[8]*alpha+p*v2.x; acc[9]=acc[9]*alpha+p*v2.y;
            acc[10]=acc[10]*alpha+p*v2.z; acc[11]=acc[11]*alpha+p*v2.w;
            acc[12]=acc[12]*alpha+p*v3.x; acc[13]=acc[13]*alpha+p*v3.y;
            acc[14]=acc[14]*alpha+p*v3.z; acc[15]=acc[15]*alpha+p*v3.w;
            m = nm;
        }
    }

    #pragma unroll
    for (int mask = 4; mask < 32; mask <<= 1){
        float m2 = __shfl_xor_sync(0xffffffffu, m, mask);
        float l2 = __shfl_xor_sync(0xffffffffu, l, mask);
        float nm = fmaxf(m, m2);
        float a1 = __expf(m - nm), a2 = __expf(m2 - nm);
        l = l*a1 + l2*a2;
        #pragma unroll
        for (int j = 0; j < 16; j++){
            float o = __shfl_xor_sync(0xffffffffu, acc[j], mask);
            acc[j] = acc[j]*a1 + o*a2;
        }
        m = nm;
    }
    if (g == 0){
        float inv = 1.f / l;
        float* yr = Y + (size_t)(b*SS + qi)*DD + h*64 + qd*16;
        #pragma unroll
        for (int j = 0; j < 4; j++){
            float4 o = { tfr(acc[j*4]*inv), tfr(acc[j*4+1]*inv),
                         tfr(acc[j*4+2]*inv), tfr(acc[j*4+3]*inv) };
            *(float4*)(yr + j*4) = o;
        }
    }
}

// ---------------- orchestration ---------------------------------------------
extern "C" void kernel_launch(void* const* d_in, const int* in_sizes, int n_in,
                              void* d_out, int out_size)
{
    const int*   tokens  = (const int*)  d_in[0];
    const float* tok_emb = (const float*)d_in[1];
    const float* Wq = (const float*)d_in[2];  const float* bq = (const float*)d_in[3];
    const float* Wk = (const float*)d_in[4];  const float* bk = (const float*)d_in[5];
    const float* Wv = (const float*)d_in[6];  const float* bv = (const float*)d_in[7];
    const float* Wo = (const float*)d_in[8];  const float* bo = (const float*)d_in[9];
    const float* ln1g = (const float*)d_in[10]; const float* ln1b = (const float*)d_in[11];
    const float* ln2g = (const float*)d_in[12]; const float* ln2b = (const float*)d_in[13];
    const float* W1 = (const float*)d_in[14]; const float* b1 = (const float*)d_in[15];
    const float* W2 = (const float*)d_in[16]; const float* b2 = (const float*)d_in[17];
    const float* lnfg = (const float*)d_in[18]; const float* lnfb = (const float*)d_in[19];
    const float* fcW = (const float*)d_in[20]; const float* fcb = (const float*)d_in[21];

    float *x, *h, *qkv, *y, *ff, *bqkv, *wt;
    cudaGetSymbolAddress((void**)&x,    g_x);
    cudaGetSymbolAddress((void**)&h,    g_h);
    cudaGetSymbolAddress((void**)&qkv,  g_qkv);
    cudaGetSymbolAddress((void**)&y,    g_y);
    cudaGetSymbolAddress((void**)&ff,   g_ff);
    cudaGetSymbolAddress((void**)&bqkv, g_bqkv);
    cudaGetSymbolAddress((void**)&wt,   g_wt);

    const int SMEM4 = (3*128*32 + 3*32*136) * 4;   // 101376 B (2 CTA/SM: 203KB)
    const int SMEM2 = (3*128*32 + 3*32*72)  * 4;   //  76800 B
    cudaFuncSetAttribute((const void*)mma_gemm<4,2>, cudaFuncAttributeMaxDynamicSharedMemorySize, SMEM4);
    cudaFuncSetAttribute((const void*)mma_gemm<2,2>, cudaFuncAttributeMaxDynamicSharedMemorySize, SMEM2);

    // Launch order tuned so ncu (-s 5 -c 1) captures the layer-0 QKV GEMM (#5).
    embed_kernel<<<MM, 256>>>(tokens, tok_emb, x);                               // 0
    pack_bias<<<(LL*QKVN + 255)/256, 256>>>(bq, bk, bv, bqkv);                   // 1
    pack_qkvw<<<(LL*768*2304/4 + 255)/256, 256>>>(Wq, Wk, Wv, wt + WT_QKV);      // 2
    round_copy<<<(LL*589824/4 + 255)/256, 256>>>(Wo, wt + WT_O, LL*589824/4);    // 3
    ln_kernel<<<MM, 256>>>(x, ln1g, ln1b, h);                                    // 4 (layer 0 ln1)
    mma_gemm<4,2><<<dim3(MM/128, QKVN/128), 256, SMEM4>>>(h, wt + WT_QKV,        // 5 <- profiled
                                                          bqkv, nullptr, qkv, QKVN, DD, 0);
    round_copy<<<(LL*2359296/4 + 255)/256, 256>>>(W1, wt + WT_W1, LL*2359296/4); // 6
    round_copy<<<(LL*2359296/4 + 255)/256, 256>>>(W2, wt + WT_W2, LL*2359296/4); // 7
    round_copy<<<(24576000/4   + 255)/256, 256>>>(fcW, wt + WT_FC, 24576000/4);  // 8

    for (int l = 0; l < LL; l++){
        if (l > 0){
            ln_kernel<<<MM, 256>>>(x, ln1g + l*DD, ln1b + l*DD, h);
            mma_gemm<4,2><<<dim3(MM/128, QKVN/128), 256, SMEM4>>>(h, wt + WT_QKV + l*WT_QKV_L,
                                                                  bqkv + l*QKVN, nullptr, qkv, QKVN, DD, 0);
        }
        attn_kernel<<<BB*HH*(SS/8), 256>>>(qkv, y);
        mma_gemm<2,2><<<dim3(MM/128, DD/64), 256, SMEM2>>>(y, wt + WT_O + l*WT_O_L,
                                                           bo + l*DD, x, x, DD, DD, 0);
        ln_kernel<<<MM, 256>>>(x, ln2g + l*DD, ln2b + l*DD, h);
        mma_gemm<4,2><<<dim3(MM/128, FF/128), 256, SMEM4>>>(h, wt + WT_W1 + l*WT_W1_L,
                                                            b1 + l*FF, nullptr, ff, FF, DD, 1);
        mma_gemm<2,2><<<dim3(MM/128, DD/64), 256, SMEM2>>>(ff, wt + WT_W2 + l*WT_W2_L,
                                                           b2 + l*DD, x, x, DD, FF, 0);
    }
    ln_kernel<<<MM, 256>>>(x, lnfg, lnfb, h);
    mma_gemm<4,2><<<dim3(MM/128, VV/128), 256, SMEM4>>>(h, wt + WT_FC, fcb, nullptr,
                                                        (float*)d_out, VV, DD, 0);
}

// round 14
// speedup vs baseline: 2.6050x; 1.1839x over previous
#include <cuda_runtime.h>
#include <cuda_fp16.h>
#include <math.h>
#include <stdint.h>

#define BB 2
#define SS 1024
#define DD 768
#define HH 12
#define LL 4
#define VV 32000
#define MM (BB*SS)      // 2048
#define FF (4*DD)       // 3072
#define QKVN (3*DD)     // 2304

// ---------------- scratch (device globals) ----------------------------------
__device__ float  g_x  [MM*DD];
__device__ __half g_h  [MM*DD];    // ln outputs (GEMM A input)
__device__ float  g_qkv[MM*QKVN];  // fp32: attention math stays fp32
__device__ __half g_y  [MM*DD];    // attn output
__device__ __half g_ff [MM*FF];    // gelu output
__device__ float  g_bqkv[LL*QKVN];
__device__ __half g_wt [52887552]; // fp16 weights, NATURAL [K][N] layout

#define WT_QKV   0u
#define WT_QKV_L 1769472u           // [768][2304] per layer
#define WT_O     7077888u
#define WT_O_L   589824u            // [768][768]
#define WT_W1    9437184u
#define WT_W1_L  2359296u           // [768][3072]
#define WT_W2    18874368u
#define WT_W2_L  2359296u           // [3072][768]
#define WT_FC    28311552u          // [768][32000]

__device__ __forceinline__ uint32_t smem_u32(const void* p){
    uint32_t r;
    asm("{ .reg .u64 t; cvta.to.shared.u64 t, %1; cvt.u32.u64 %0, t; }" : "=r"(r) : "l"(p));
    return r;
}

#define MMA16(d, a0,a1,a2,a3, b0,b1) \
  asm volatile("mma.sync.aligned.m16n8k16.row.col.f32.f16.f16.f32 " \
      "{%0,%1,%2,%3}, {%4,%5,%6,%7}, {%8,%9}, {%0,%1,%2,%3};" \
      : "+f"(d.x),"+f"(d.y),"+f"(d.z),"+f"(d.w) \
      : "r"(a0),"r"(a1),"r"(a2),"r"(a3), "r"(b0),"r"(b1))

#define CP_ASYNC16(dst, src) \
  asm volatile("cp.async.cg.shared.global [%0], [%1], 16;" :: "r"(dst), "l"(src))
#define CP_COMMIT()  asm volatile("cp.async.commit_group;" ::: "memory")
#define CP_WAIT1()   asm volatile("cp.async.wait_group 1;" ::: "memory")

// ---------------- embedding + positional encoding ---------------------------
__global__ void embed_kernel(const int* __restrict__ tokens,
                             const float* __restrict__ tok_emb,
                             float* __restrict__ x)
{
    int row = blockIdx.x;
    int pos = row % SS;
    int tok = tokens[row];
    const float sc = sqrtf((float)DD);
    const float negl = -logf(10000.0f) / (float)DD;
    for (int d = threadIdx.x; d < DD; d += blockDim.x) {
        int i2 = (d >> 1) << 1;
        float div = __expf((float)i2 * negl);
        float ang = (float)pos * div;
        float pe = (d & 1) ? cosf(ang) : sinf(ang);
        x[(size_t)row*DD + d] = tok_emb[(size_t)tok*DD + d] * sc + pe;
    }
}

// ---------------- layernorm (writes fp16 output: GEMM A input) ---------------
__global__ void __launch_bounds__(256) ln_kernel(const float* __restrict__ X,
                                                 const float* __restrict__ g,
                                                 const float* __restrict__ b,
                                                 __half* __restrict__ O)
{
    __shared__ float red[8];
    __shared__ float s_mean, s_rstd;
    int row = blockIdx.x, tid = threadIdx.x;
    const float* xr = X + (size_t)row*DD;
    float v0 = xr[tid], v1 = xr[tid+256], v2 = xr[tid+512];
    float s = v0 + v1 + v2;
    #pragma unroll
    for (int o = 16; o; o >>= 1) s += __shfl_xor_sync(0xffffffffu, s, o);
    if ((tid & 31) == 0) red[tid >> 5] = s;
    __syncthreads();
    if (tid == 0) {
        float t = 0.f;
        #pragma unroll
        for (int i = 0; i < 8; i++) t += red[i];
        s_mean = t / (float)DD;
    }
    __syncthreads();
    float mu = s_mean;
    float d0 = v0-mu, d1 = v1-mu, d2 = v2-mu;
    s = d0*d0 + d1*d1 + d2*d2;
    #pragma unroll
    for (int o = 16; o; o >>= 1) s += __shfl_xor_sync(0xffffffffu, s, o);
    if ((tid & 31) == 0) red[tid >> 5] = s;
    __syncthreads();
    if (tid == 0) {
        float t = 0.f;
        #pragma unroll
        for (int i = 0; i < 8; i++) t += red[i];
        s_rstd = rsqrtf(t / (float)DD + 1e-5f);
    }
    __syncthreads();
    float r = s_rstd;
    size_t base = (size_t)row*DD;
    O[base+tid    ] = __float2half_rn(d0*r*g[tid    ] + b[tid    ]);
    O[base+tid+256] = __float2half_rn(d1*r*g[tid+256] + b[tid+256]);
    O[base+tid+512] = __float2half_rn(d2*r*g[tid+512] + b[tid+512]);
}

// ---------------- pre-pass: fp32 -> fp16 coalesced converts ------------------
__global__ void hconv(const float* __restrict__ in, __half* __restrict__ out, int n4)
{
    int i = blockIdx.x*256 + threadIdx.x;
    if (i < n4){
        float4 v = ((const float4*)in)[i];
        __half2 h0 = __floats2half2_rn(v.x, v.y);
        __half2 h1 = __floats2half2_rn(v.z, v.w);
        uint2 o = { *(uint32_t*)&h0, *(uint32_t*)&h1 };
        ((uint2*)out)[i] = o;
    }
}

// fused: [768][2304] = [Wq|Wk|Wv] per layer as fp16 + qkv bias packing
__global__ void pack_qkvw(const float* __restrict__ Wq, const float* __restrict__ Wk,
                          const float* __restrict__ Wv,
                          const float* __restrict__ bq, const float* __restrict__ bk,
                          const float* __restrict__ bv,
                          __half* __restrict__ out, float* __restrict__ bout)
{
    int blk = blockIdx.x;
    if (blk >= 6912){
        int idx = (blk - 6912)*256 + threadIdx.x;
        if (idx < LL*QKVN){
            int l = idx / QKVN, n = idx % QKVN;
            bout[idx] = (n < 768) ? bq[l*768 + n]
                      : (n < 1536) ? bk[l*768 + n - 768]
                                   : bv[l*768 + n - 1536];
        }
        return;
    }
    int i = blk*256 + threadIdx.x;
    int n4 = i % 576;                  // 2304/4
    int lk = i / 576;                  // l*768 + k
    int sel = n4 / 192;
    int n4s = n4 - sel*192;
    const float* src = (sel == 0) ? Wq : (sel == 1) ? Wk : Wv;
    float4 v = ((const float4*)src)[(size_t)lk*192 + n4s];
    __half2 h0 = __floats2half2_rn(v.x, v.y);
    __half2 h1 = __floats2half2_rn(v.z, v.w);
    uint2 o = { *(uint32_t*)&h0, *(uint32_t*)&h1 };
    ((uint2*)out)[i] = o;
}

// ---------------- fp16 mma.sync GEMM (m16n8k16), 3-stage cp.async ------------
// C[2048,N] = act(A[2048,K] @ B[K,N] + bias [+ res]); A,B fp16, accum fp32.
// CTA tile 128 x (32*WNT), BK=32, 8 warps (2m x 4n), warp tile 64 x (8*WNT).
// A SMEM: [row][32 halves] pitch 40 halves (80B): fragment LDS.32 bank = 20g+t
//   (bijective over warp, conflict-free); cp.async-writable (16B chunks).
// B SMEM: [k][n] pitch BN+8 halves; row stride == 16 mod 128 B -> conflict-free
//   ldmatrix.x4.trans (canonical B-fragment path for row.col mma, [K][N] global).
template<int WNT, int MINB>
__global__ void __launch_bounds__(256, MINB) hgemm(
    const __half* __restrict__ A, const __half* __restrict__ B,
    const float* __restrict__ bias, const float* __restrict__ res,
    float* __restrict__ C, __half* __restrict__ Ch, int N, int K, int act)
{
    const int BN   = 32*WNT;
    const int BNPH = BN + 8;            // halves pitch for B k-rows
    const int ASZ  = 128*80;            // bytes per A stage
    const int BSZ  = 32*BNPH*2;         // bytes per B stage
    extern __shared__ char smraw[];
    char* As = smraw;                   // 3 * ASZ
    char* Bs = smraw + 3*ASZ;           // 3 * BSZ
    uint32_t uAs = smem_u32(As);
    uint32_t uBs = smem_u32(Bs);

    int tid = threadIdx.x;
    int wid = tid >> 5, lane = tid & 31;
    int g = lane >> 2, t = lane & 3;
    int wm = wid & 1, wn = wid >> 1;
    int bm = blockIdx.x * 128, bn = blockIdx.y * BN;

    float4 acc[4][WNT];
    #pragma unroll
    for (int i = 0; i < 4; i++)
        #pragma unroll
        for (int j = 0; j < WNT; j++)
            acc[i][j] = make_float4(0.f,0.f,0.f,0.f);

    // A copy: 128 rows x 4 chunks(16B); thread -> row = tid>>1, chunks (tid&1)*2+{0,1}
    int arow = tid >> 1, acp = (tid & 1)*2;
    const __half* Ag = A + (size_t)(bm + arow)*K;
    auto cpA = [&](int kt, int stg){
        uint32_t dst = uAs + stg*ASZ + arow*80 + acp*16;
        const __half* s = Ag + kt*32 + acp*8;
        CP_ASYNC16(dst,      s);
        CP_ASYNC16(dst + 16, s + 8);
    };
    // B copy: 32 k-rows x (BN/8) chunks
    auto cpB = [&](int kt, int stg){
        int kr = tid >> 3;
        const __half* s0 = B + (size_t)(kt*32 + kr)*N + bn;
        uint32_t dst0 = uBs + stg*BSZ + kr*(BNPH*2);
        if (WNT == 4){
            int cp = (tid & 7)*2;
            CP_ASYNC16(dst0 + cp*16,      s0 + cp*8);
            CP_ASYNC16(dst0 + cp*16 + 16, s0 + cp*8 + 8);
        } else {
            int cp = tid & 7;
            CP_ASYNC16(dst0 + cp*16, s0 + cp*8);
        }
    };

    cpA(0,0); cpB(0,0); CP_COMMIT();
    cpA(1,1); cpB(1,1); CP_COMMIT();

    const int NK = K / 32;
    int stg = 0;
    for (int kt = 0; kt < NK; kt++){
        CP_WAIT1();
        __syncthreads();
        int pf = kt + 2;
        if (pf < NK){
            int ps = stg - 1; if (ps < 0) ps = 2;
            cpA(pf, ps); cpB(pf, ps);
        }
        CP_COMMIT();

        const char* Ab = As + stg*ASZ;
        uint32_t    Bb = uBs + stg*BSZ;
        #pragma unroll
        for (int j = 0; j < 2; j++){          // k16-steps
            uint32_t a[4][4];
            #pragma unroll
            for (int mt = 0; mt < 4; mt++){
                int r0 = wm*64 + mt*16 + g;
                const char* p = Ab + r0*80 + j*32 + t*4;
                a[mt][0] = *(const uint32_t*)(p);
                a[mt][1] = *(const uint32_t*)(p + 8*80);
                a[mt][2] = *(const uint32_t*)(p + 16);
                a[mt][3] = *(const uint32_t*)(p + 8*80 + 16);
            }
            uint32_t b[WNT][2];
            #pragma unroll
            for (int ntp = 0; ntp < WNT/2; ntp++){
                int k_ = 16*j + ((lane >> 3) & 1)*8 + (lane & 7);
                int nc = wn*(8*WNT) + ntp*16 + (lane >> 4)*8;
                uint32_t addr = Bb + (uint32_t)(k_*(BNPH*2) + nc*2);
                uint32_t r0_, r1_, r2_, r3_;
                asm volatile("ldmatrix.sync.aligned.m8n8.x4.trans.shared.b16 "
                             "{%0,%1,%2,%3}, [%4];"
                             : "=r"(r0_), "=r"(r1_), "=r"(r2_), "=r"(r3_) : "r"(addr));
                b[2*ntp][0] = r0_; b[2*ntp][1] = r1_;
                b[2*ntp+1][0] = r2_; b[2*ntp+1][1] = r3_;
            }
            #pragma unroll
            for (int mt = 0; mt < 4; mt++)
                #pragma unroll
                for (int nt = 0; nt < WNT; nt++)
                    MMA16(acc[mt][nt], a[mt][0], a[mt][1], a[mt][2], a[mt][3],
                          b[nt][0], b[nt][1]);
        }
        stg++; if (stg == 3) stg = 0;
    }

    // epilogue: bias/res/gelu in fp32; store fp32 (C) or fp16 (Ch)
    #pragma unroll
    for (int mt = 0; mt < 4; mt++){
        int r0 = bm + wm*64 + mt*16 + g;
        #pragma unroll
        for (int nt = 0; nt < WNT; nt++){
            int col = bn + wn*(8*WNT) + nt*8 + 2*t;
            float b0 = bias[col], b1 = bias[col+1];
            float4 c = acc[mt][nt];
            float v0 = c.x + b0, v1 = c.y + b1;
            float w0 = c.z + b0, w1 = c.w + b1;
            if (res){
                v0 += res[(size_t)r0*N + col];     v1 += res[(size_t)r0*N + col + 1];
                w0 += res[(size_t)(r0+8)*N + col]; w1 += res[(size_t)(r0+8)*N + col + 1];
            }
            if (act){
                v0 = 0.5f*v0*(1.0f + erff(v0*0.70710678118654752f));
                v1 = 0.5f*v1*(1.0f + erff(v1*0.70710678118654752f));
                w0 = 0.5f*w0*(1.0f + erff(w0*0.70710678118654752f));
                w1 = 0.5f*w1*(1.0f + erff(w1*0.70710678118654752f));
            }
            if (Ch){
                *(__half2*)(Ch + (size_t)r0*N + col)     = __floats2half2_rn(v0, v1);
                *(__half2*)(Ch + (size_t)(r0+8)*N + col) = __floats2half2_rn(w0, w1);
            } else {
                *(float2*)(C + (size_t)r0*N + col)     = make_float2(v0, v1);
                *(float2*)(C + (size_t)(r0+8)*N + col) = make_float2(w0, w1);
            }
        }
    }
}

// ---------------- attention: fp32 math on fp32 qkv; writes fp16 y ------------
__global__ void __launch_bounds__(256) attn_kernel(const float* __restrict__ QKV,
                                                   __half* __restrict__ Y)
{
    int wid = threadIdx.x >> 5, lane = threadIdx.x & 31;
    int g  = lane >> 2;
    int qd = lane & 3;
    int blk  = blockIdx.x;
    int qblk = blk & 127;
    int bh   = blk >> 7;
    int h = bh % HH, b = bh / HH;
    int qi = qblk*8 + wid;

    const float* qr = QKV + (size_t)(b*SS + qi)*QKVN + h*64 + qd*16;
    float4 q0 = *(const float4*)(qr+0),  q1 = *(const float4*)(qr+4);
    float4 q2 = *(const float4*)(qr+8),  q3 = *(const float4*)(qr+12);
    const float s8 = 0.125f;
    q0.x*=s8;q0.y*=s8;q0.z*=s8;q0.w*=s8; q1.x*=s8;q1.y*=s8;q1.z*=s8;q1.w*=s8;
    q2.x*=s8;q2.y*=s8;q2.z*=s8;q2.w*=s8; q3.x*=s8;q3.y*=s8;q3.z*=s8;q3.w*=s8;

    const float* Kb = QKV + (size_t)b*SS*QKVN + 768  + h*64 + qd*16;
    const float* Vb = QKV + (size_t)b*SS*QKVN + 1536 + h*64 + qd*16;

    float m = -1e30f, l = 0.f;
    float acc[16];
    #pragma unroll
    for (int j = 0; j < 16; j++) acc[j] = 0.f;

    int nit = (qi >> 3) + 1;
    for (int it = 0; it < nit; it++){
        int s = it*8 + g;
        const float* kr = Kb + (size_t)s*QKVN;
        float4 k0 = *(const float4*)(kr+0),  k1 = *(const float4*)(kr+4);
        float4 k2 = *(const float4*)(kr+8),  k3 = *(const float4*)(kr+12);
        float ss = q0.x*k0.x + q0.y*k0.y + q0.z*k0.z + q0.w*k0.w
                 + q1.x*k1.x + q1.y*k1.y + q1.z*k1.z + q1.w*k1.w
                 + q2.x*k2.x + q2.y*k2.y + q2.z*k2.z + q2.w*k2.w
                 + q3.x*k3.x + q3.y*k3.y + q3.z*k3.z + q3.w*k3.w;
        ss += __shfl_xor_sync(0xffffffffu, ss, 1);
        ss += __shfl_xor_sync(0xffffffffu, ss, 2);
        if (s <= qi){
            float nm = fmaxf(m, ss);
            float alpha = __expf(m - nm);
            float p = __expf(ss - nm);
            l = l*alpha + p;
            const float* vr = Vb + (size_t)s*QKVN;
            float4 v0 = *(const float4*)(vr+0),  v1 = *(const float4*)(vr+4);
            float4 v2 = *(const float4*)(vr+8),  v3 = *(const float4*)(vr+12);
            acc[0]=acc[0]*alpha+p*v0.x; acc[1]=acc[1]*alpha+p*v0.y;
            acc[2]=acc[2]*alpha+p*v0.z; acc[3]=acc[3]*alpha+p*v0.w;
            acc[4]=acc[4]*alpha+p*v1.x; acc[5]=acc[5]*alpha+p*v1.y;
            acc[6]=acc[6]*alpha+p*v1.z; acc[7]=acc[7]*alpha+p*v1.w;
            acc[8]=acc[8]*alpha+p*v2.x; acc[9]=acc[9]*alpha+p*v2.y;
            acc[10]=acc[10]*alpha+p*v2.z; acc[11]=acc[11]*alpha+p*v2.w;
            acc[12]=acc[12]*alpha+p*v3.x; acc[13]=acc[13]*alpha+p*v3.y;
            acc[14]=acc[14]*alpha+p*v3.z; acc[15]=acc[15]*alpha+p*v3.w;
            m = nm;
        }
    }

    #pragma unroll
    for (int mask = 4; mask < 32; mask <<= 1){
        float m2 = __shfl_xor_sync(0xffffffffu, m, mask);
        float l2 = __shfl_xor_sync(0xffffffffu, l, mask);
        float nm = fmaxf(m, m2);
        float a1 = __expf(m - nm), a2 = __expf(m2 - nm);
        l = l*a1 + l2*a2;
        #pragma unroll
        for (int j = 0; j < 16; j++){
            float o = __shfl_xor_sync(0xffffffffu, acc[j], mask);
            acc[j] = acc[j]*a1 + o*a2;
        }
        m = nm;
    }
    if (g == 0){
        float inv = 1.f / l;
        __half2* yr = (__half2*)(Y + (size_t)(b*SS + qi)*DD + h*64 + qd*16);
        #pragma unroll
        for (int j = 0; j < 4; j++){
            yr[j*2    ] = __floats2half2_rn(acc[j*4]*inv,   acc[j*4+1]*inv);
            yr[j*2 + 1] = __floats2half2_rn(acc[j*4+2]*inv, acc[j*4+3]*inv);
        }
    }
}

// ---------------- orchestration ---------------------------------------------
extern "C" void kernel_launch(void* const* d_in, const int* in_sizes, int n_in,
                              void* d_out, int out_size)
{
    const int*   tokens  = (const int*)  d_in[0];
    const float* tok_emb = (const float*)d_in[1];
    const float* Wq = (const float*)d_in[2];  const float* bq = (const float*)d_in[3];
    const float* Wk = (const float*)d_in[4];  const float* bk = (const float*)d_in[5];
    const float* Wv = (const float*)d_in[6];  const float* bv = (const float*)d_in[7];
    const float* Wo = (const float*)d_in[8];  const float* bo = (const float*)d_in[9];
    const float* ln1g = (const float*)d_in[10]; const float* ln1b = (const float*)d_in[11];
    const float* ln2g = (const float*)d_in[12]; const float* ln2b = (const float*)d_in[13];
    const float* W1 = (const float*)d_in[14]; const float* b1 = (const float*)d_in[15];
    const float* W2 = (const float*)d_in[16]; const float* b2 = (const float*)d_in[17];
    const float* lnfg = (const float*)d_in[18]; const float* lnfb = (const float*)d_in[19];
    const float* fcW = (const float*)d_in[20]; const float* fcb = (const float*)d_in[21];

    float *x, *qkv, *bqkv;
    __half *h, *y, *ff, *wt;
    cudaGetSymbolAddress((void**)&x,    g_x);
    cudaGetSymbolAddress((void**)&h,    g_h);
    cudaGetSymbolAddress((void**)&qkv,  g_qkv);
    cudaGetSymbolAddress((void**)&y,    g_y);
    cudaGetSymbolAddress((void**)&ff,   g_ff);
    cudaGetSymbolAddress((void**)&bqkv, g_bqkv);
    cudaGetSymbolAddress((void**)&wt,   g_wt);

    const int SMEM4 = 3*128*80 + 3*32*136*2;   // 56832 B
    const int SMEM2 = 3*128*80 + 3*32*72*2;    // 44544 B
    cudaFuncSetAttribute((const void*)hgemm<4,2>, cudaFuncAttributeMaxDynamicSharedMemorySize, SMEM4);
    cudaFuncSetAttribute((const void*)hgemm<2,2>, cudaFuncAttributeMaxDynamicSharedMemorySize, SMEM2);

    // Order so the first hgemm is our 4th launch (ncu -s 5 with harness preamble).
    embed_kernel<<<MM, 256>>>(tokens, tok_emb, x);                                 // 0
    pack_qkvw<<<6948, 256>>>(Wq, Wk, Wv, bq, bk, bv, wt + WT_QKV, bqkv);           // 1
    ln_kernel<<<MM, 256>>>(x, ln1g, ln1b, h);                                      // 2
    hgemm<4,2><<<dim3(MM/128, QKVN/128), 256, SMEM4>>>(h, wt + WT_QKV,             // 3 <- target
        bqkv, nullptr, qkv, nullptr, QKVN, DD, 0);
    hconv<<<(LL*589824/4  + 255)/256, 256>>>(Wo,  wt + WT_O,  LL*589824/4);        // 4
    hconv<<<(LL*2359296/4 + 255)/256, 256>>>(W1,  wt + WT_W1, LL*2359296/4);       // 5
    hconv<<<(LL*2359296/4 + 255)/256, 256>>>(W2,  wt + WT_W2, LL*2359296/4);       // 6
    hconv<<<(24576000/4   + 255)/256, 256>>>(fcW, wt + WT_FC, 24576000/4);         // 7

    for (int l = 0; l < LL; l++){
        if (l > 0){
            ln_kernel<<<MM, 256>>>(x, ln1g + l*DD, ln1b + l*DD, h);
            hgemm<4,2><<<dim3(MM/128, QKVN/128), 256, SMEM4>>>(h, wt + WT_QKV + l*WT_QKV_L,
                bqkv + l*QKVN, nullptr, qkv, nullptr, QKVN, DD, 0);
        }
        attn_kernel<<<BB*HH*(SS/8), 256>>>(qkv, y);
        hgemm<2,2><<<dim3(MM/128, DD/64), 256, SMEM2>>>(y, wt + WT_O + l*WT_O_L,
            bo + l*DD, x, x, nullptr, DD, DD, 0);
        ln_kernel<<<MM, 256>>>(x, ln2g + l*DD, ln2b + l*DD, h);
        hgemm<4,2><<<dim3(MM/128, FF/128), 256, SMEM4>>>(h, wt + WT_W1 + l*WT_W1_L,
            b1 + l*FF, nullptr, nullptr, ff, FF, DD, 1);
        hgemm<2,2><<<dim3(MM/128, DD/64), 256, SMEM2>>>(ff, wt + WT_W2 + l*WT_W2_L,
            b2 + l*DD, x, x, nullptr, DD, FF, 0);
    }
    ln_kernel<<<MM, 256>>>(x, lnfg, lnfb, h);
    hgemm<4,2><<<dim3(MM/128, VV/128), 256, SMEM4>>>(h, wt + WT_FC, fcb, nullptr,
        (float*)d_out, nullptr, VV, DD, 0);
}